// round 2
// baseline (speedup 1.0000x reference)
#include <cuda_runtime.h>
#include <cuda_bf16.h>
#include <cstdint>

#define NN 50000
#define NE 800000
#define NG 512
#define H  128
#define NL 4

// ---------------- device scratch (static, no allocations) ----------------
__device__ float g_E  [(size_t)NN * 2 * H];   // init embedding input [NN,256]
__device__ float g_x  [(size_t)NN * H];       // node features
__device__ float g_y  [(size_t)NN * H];       // temp (between the two GIN GEMMs)
__device__ float g_agg[(size_t)NN * H];       // neighbor sums
__device__ float g_pool[(size_t)NG * H];      // pooled per-graph features
__device__ float g_ho [4 * NG];               // raw head outputs

// ---------------- small helpers ----------------
__device__ __forceinline__ float softplusf(float x) {
    return fmaxf(x, 0.f) + log1pf(expf(-fabsf(x)));
}

__device__ __forceinline__ int lbound(const int* __restrict__ a, int n, int v) {
    int lo = 0, hi = n;
    while (lo < hi) { int m = (lo + hi) >> 1; if (a[m] < v) lo = m + 1; else hi = m; }
    return lo;
}

// ---------------- kernel: build E = [embed_tab[z], pos@W_pos + b_pos] ----------------
__global__ void build_embed_kernel(const int* __restrict__ z, const float* __restrict__ pos,
                                   const float* __restrict__ tab, const float* __restrict__ Wp,
                                   const float* __restrict__ bp, float* __restrict__ E) {
    int gid = blockIdx.x * blockDim.x + threadIdx.x;
    if (gid >= NN * 64) return;
    int i = gid >> 6;
    int j = gid & 63;
    if (j < 32) {
        int c = j * 4;
        float4 v = *(const float4*)(tab + (size_t)z[i] * H + c);
        *(float4*)(E + (size_t)i * 256 + c) = v;
    } else {
        int c = (j - 32) * 4;
        float p0 = pos[i * 3 + 0], p1 = pos[i * 3 + 1], p2 = pos[i * 3 + 2];
        float4 v;
        v.x = p0 * Wp[0 * H + c + 0] + p1 * Wp[1 * H + c + 0] + p2 * Wp[2 * H + c + 0] + bp[c + 0];
        v.y = p0 * Wp[0 * H + c + 1] + p1 * Wp[1 * H + c + 1] + p2 * Wp[2 * H + c + 1] + bp[c + 1];
        v.z = p0 * Wp[0 * H + c + 2] + p1 * Wp[1 * H + c + 2] + p2 * Wp[2 * H + c + 2] + bp[c + 2];
        v.w = p0 * Wp[0 * H + c + 3] + p1 * Wp[1 * H + c + 3] + p2 * Wp[2 * H + c + 3] + bp[c + 3];
        *(float4*)(E + (size_t)i * 256 + 128 + c) = v;
    }
}

// ---------------- kernel: zero float buffer ----------------
__global__ void zero_kernel(float4* __restrict__ p, int n4) {
    int i = blockIdx.x * blockDim.x + threadIdx.x;
    if (i < n4) p[i] = make_float4(0.f, 0.f, 0.f, 0.f);
}

// ---------------- kernel: edge scatter-add (agg[dst] += x[src]) ----------------
__global__ void scatter_kernel(const float* __restrict__ x, const int* __restrict__ src,
                               const int* __restrict__ dst, float* __restrict__ agg) {
    int gid = blockIdx.x * blockDim.x + threadIdx.x;
    int e = gid >> 5;
    if (e >= NE) return;
    int lane = gid & 31;
    int s = src[e];
    int d = dst[e];
    float4 v = *(const float4*)(x + (size_t)s * H + lane * 4);
    float* p = agg + (size_t)d * H + lane * 4;
    asm volatile("red.global.add.v4.f32 [%0], {%1,%2,%3,%4};"
                 :: "l"(p), "f"(v.x), "f"(v.y), "f"(v.z), "f"(v.w) : "memory");
}

// ---------------- kernel: fp32 GEMM  C[M,128] = act((A (+A2)) @ W[K,128] + b) ----------------
// BM=128, BN=128, BK=16, 256 threads, 8x8 per-thread microtile.
template<int K, bool RELU, bool HASA2>
__global__ __launch_bounds__(256)
void gemm128_kernel(const float* __restrict__ A, const float* __restrict__ A2,
                    const float* __restrict__ W, const float* __restrict__ bias,
                    float* __restrict__ C, int M) {
    __shared__ float As[16][132];   // padded to kill bank conflicts on transposed stores
    __shared__ float Ws[16][128];

    int t = threadIdx.x;
    int m0 = blockIdx.x * 128;
    int tx = t & 15;       // 0..15 -> output cols tx*4 and tx*4+64
    int ty = t >> 4;       // 0..15 -> output rows ty*4 and ty*4+64

    float acc[8][8];
#pragma unroll
    for (int i = 0; i < 8; i++)
#pragma unroll
        for (int j = 0; j < 8; j++) acc[i][j] = 0.f;

    for (int k0 = 0; k0 < K; k0 += 16) {
#pragma unroll
        for (int it = 0; it < 2; it++) {
            int idx = t + it * 256;          // 0..511
            // A tile: 128 rows x 16 cols = 512 float4 (transpose into As)
            int row = idx >> 2;
            int kq  = (idx & 3) * 4;
            int grow = m0 + row;
            float4 a = make_float4(0.f, 0.f, 0.f, 0.f);
            if (grow < M) {
                a = *(const float4*)(A + (size_t)grow * K + k0 + kq);
                if (HASA2) {
                    float4 b = *(const float4*)(A2 + (size_t)grow * K + k0 + kq);
                    a.x += b.x; a.y += b.y; a.z += b.z; a.w += b.w;
                }
            }
            As[kq + 0][row] = a.x;
            As[kq + 1][row] = a.y;
            As[kq + 2][row] = a.z;
            As[kq + 3][row] = a.w;
            // W tile: 16 rows x 128 cols = 512 float4
            int wr = idx >> 5;
            int wc = (idx & 31) * 4;
            *(float4*)&Ws[wr][wc] = *(const float4*)(W + (size_t)(k0 + wr) * 128 + wc);
        }
        __syncthreads();

#pragma unroll
        for (int kk = 0; kk < 16; kk++) {
            float a[8], w[8];
            *(float4*)&a[0] = *(const float4*)&As[kk][ty * 4];
            *(float4*)&a[4] = *(const float4*)&As[kk][ty * 4 + 64];
            *(float4*)&w[0] = *(const float4*)&Ws[kk][tx * 4];
            *(float4*)&w[4] = *(const float4*)&Ws[kk][tx * 4 + 64];
#pragma unroll
            for (int i = 0; i < 8; i++)
#pragma unroll
                for (int j = 0; j < 8; j++)
                    acc[i][j] = fmaf(a[i], w[j], acc[i][j]);
        }
        __syncthreads();
    }

    // epilogue
#pragma unroll
    for (int i = 0; i < 8; i++) {
        int row = m0 + ty * 4 + (i & 3) + ((i >> 2) << 6);
        if (row >= M) continue;
#pragma unroll
        for (int jh = 0; jh < 2; jh++) {
            int col = tx * 4 + jh * 64;
            float4 v;
            v.x = acc[i][jh * 4 + 0] + bias[col + 0];
            v.y = acc[i][jh * 4 + 1] + bias[col + 1];
            v.z = acc[i][jh * 4 + 2] + bias[col + 2];
            v.w = acc[i][jh * 4 + 3] + bias[col + 3];
            if (RELU) {
                v.x = fmaxf(v.x, 0.f); v.y = fmaxf(v.y, 0.f);
                v.z = fmaxf(v.z, 0.f); v.w = fmaxf(v.w, 0.f);
            }
            *(float4*)(C + (size_t)row * 128 + col) = v;
        }
    }
}

// ---------------- kernel: per-graph sum pooling (batch is sorted) ----------------
__global__ void pool_kernel(const float* __restrict__ x, const int* __restrict__ batch,
                            float* __restrict__ pool) {
    int g = blockIdx.x;
    int f = threadIdx.x;   // 0..127
    __shared__ int slo, shi;
    if (f == 0) {
        slo = lbound(batch, NN, g);
        shi = lbound(batch, NN, g + 1);
    }
    __syncthreads();
    float s = 0.f;
    for (int i = slo; i < shi; i++) s += x[(size_t)i * H + f];
    pool[(size_t)g * H + f] = s;
}

// ---------------- kernel: 4 heads, Linear-ReLU-Linear over pooled features ----------------
__global__ void heads_kernel(const float* __restrict__ pool, const float* __restrict__ W1,
                             const float* __restrict__ b1, const float* __restrict__ W2,
                             const float* __restrict__ b2, float* __restrict__ hout) {
    int k  = blockIdx.x;   // head 0..3
    int gc = blockIdx.y;   // graph chunk 0..31 (16 graphs each)
    int f  = threadIdx.x;  // 0..127
    __shared__ float rows[16][128];
    __shared__ float red[16][128];
    int g0 = gc * 16;
#pragma unroll
    for (int g = 0; g < 16; g++) rows[g][f] = pool[(size_t)(g0 + g) * H + f];
    __syncthreads();

    const float* W1k = W1 + (size_t)k * H * H;
    float acc[16];
#pragma unroll
    for (int g = 0; g < 16; g++) acc[g] = 0.f;
    for (int h = 0; h < 128; h++) {
        float w = W1k[(size_t)h * H + f];
#pragma unroll
        for (int g = 0; g < 16; g++) acc[g] = fmaf(rows[g][h], w, acc[g]);
    }
    float bb = b1[k * H + f];
    float w2 = W2[k * H + f];
#pragma unroll
    for (int g = 0; g < 16; g++) red[g][f] = fmaxf(acc[g] + bb, 0.f) * w2;
    __syncthreads();
    if (f < 16) {
        float s = 0.f;
        for (int h = 0; h < 128; h++) s += red[f][h];
        hout[k * NG + g0 + f] = s + b2[k];
    }
}

// ---------------- kernel: evidential epilogue ----------------
__global__ void final_kernel(const float* __restrict__ ho, float* __restrict__ out) {
    int g = blockIdx.x * blockDim.x + threadIdx.x;
    if (g >= NG) return;
    float o0 = ho[0 * NG + g];
    float o1 = ho[1 * NG + g];
    float o2 = ho[2 * NG + g];
    float o3 = ho[3 * NG + g];
    float alpha = fmaxf(softplusf(o0) + 1.f, 1.f + 1e-4f);
    float beta  = softplusf(o1);
    float nu    = softplusf(o2);
    float am1   = alpha - 1.f;
    out[0 * NG + g] = o3;                 // gamma
    out[1 * NG + g] = beta / am1;         // aleatoric
    out[2 * NG + g] = beta / (am1 * nu);  // epistemic
    out[3 * NG + g] = nu;
    out[4 * NG + g] = alpha;
    out[5 * NG + g] = beta;
}

// ---------------- launch ----------------
extern "C" void kernel_launch(void* const* d_in, const int* in_sizes, int n_in,
                              void* d_out, int out_size) {
    const int*   z      = (const int*)  d_in[0];
    const float* pos    = (const float*)d_in[1];
    const int*   batch  = (const int*)  d_in[2];
    const int*   eidx   = (const int*)  d_in[3];   // [2, NE]: row0 src, row1 dst
    const float* tab    = (const float*)d_in[4];
    const float* Wp     = (const float*)d_in[5];
    const float* bp     = (const float*)d_in[6];
    const float* Wcomb  = (const float*)d_in[7];
    const float* bcomb  = (const float*)d_in[8];
    const float* gW1    = (const float*)d_in[9];
    const float* gb1    = (const float*)d_in[10];
    const float* gW2    = (const float*)d_in[11];
    const float* gb2    = (const float*)d_in[12];
    const float* hW1    = (const float*)d_in[13];
    const float* hb1    = (const float*)d_in[14];
    const float* hW2    = (const float*)d_in[15];
    const float* hb2    = (const float*)d_in[16];
    float* out = (float*)d_out;

    float *E, *x, *y, *agg, *pool, *ho;
    cudaGetSymbolAddress((void**)&E,    g_E);
    cudaGetSymbolAddress((void**)&x,    g_x);
    cudaGetSymbolAddress((void**)&y,    g_y);
    cudaGetSymbolAddress((void**)&agg,  g_agg);
    cudaGetSymbolAddress((void**)&pool, g_pool);
    cudaGetSymbolAddress((void**)&ho,   g_ho);

    const int gemm_grid = (NN + 127) / 128;   // 391

    // 1) initial embedding input
    build_embed_kernel<<<(NN * 64 + 255) / 256, 256>>>(z, pos, tab, Wp, bp, E);
    // 2) x = relu(E @ W_comb + b_comb)
    gemm128_kernel<256, true, false><<<gemm_grid, 256>>>(E, nullptr, Wcomb, bcomb, x, NN);

    // 3) GIN layers
    for (int l = 0; l < NL; l++) {
        zero_kernel<<<(NN * H / 4 + 255) / 256, 256>>>((float4*)agg, NN * H / 4);
        scatter_kernel<<<(NE * 32) / 256, 256>>>(x, eidx, eidx + NE, agg);
        gemm128_kernel<128, true, true><<<gemm_grid, 256>>>(
            x, agg, gW1 + (size_t)l * H * H, gb1 + (size_t)l * H, y, NN);
        if (l < NL - 1) {
            gemm128_kernel<128, true, false><<<gemm_grid, 256>>>(
                y, nullptr, gW2 + (size_t)l * H * H, gb2 + (size_t)l * H, x, NN);
        } else {
            gemm128_kernel<128, false, false><<<gemm_grid, 256>>>(
                y, nullptr, gW2 + (size_t)l * H * H, gb2 + (size_t)l * H, x, NN);
        }
    }

    // 4) pooling (batch sorted -> deterministic segment sums)
    pool_kernel<<<NG, 128>>>(x, batch, pool);

    // 5) heads
    heads_kernel<<<dim3(4, 32), 128>>>(pool, hW1, hb1, hW2, hb2, ho);

    // 6) evidential outputs
    final_kernel<<<2, 256>>>(ho, out);
}

// round 4
// speedup vs baseline: 1.4037x; 1.4037x over previous
#include <cuda_runtime.h>
#include <cuda_bf16.h>
#include <cstdint>

#define NN 50000
#define NE 800000
#define NG 512
#define H  128
#define NL 4

#define SCAN_B  128
#define SCAN_NB ((NN + SCAN_B - 1) / SCAN_B)   // 391

// ---------------- device scratch (static, no allocations) ----------------
__device__ float g_E  [(size_t)NN * 2 * H];   // init embedding input [NN,256]
__device__ float g_x  [(size_t)NN * H];       // node features
__device__ float g_y  [(size_t)NN * H];       // temp (between the two GIN GEMMs)
__device__ float g_agg[(size_t)NN * H];       // x + neighbor sums
__device__ float g_pool[(size_t)NG * H];      // pooled per-graph features
__device__ float g_ho [4 * NG];               // raw head outputs
// CSR scratch
__device__ int g_deg   [NN];
__device__ int g_rowptr[NN + 1];
__device__ int g_cursor[NN];
__device__ int g_col   [NE];
__device__ int g_part  [SCAN_NB];

// ---------------- small helpers ----------------
__device__ __forceinline__ float softplusf(float x) {
    return fmaxf(x, 0.f) + log1pf(expf(-fabsf(x)));
}

__device__ __forceinline__ int lbound(const int* __restrict__ a, int n, int v) {
    int lo = 0, hi = n;
    while (lo < hi) { int m = (lo + hi) >> 1; if (a[m] < v) lo = m + 1; else hi = m; }
    return lo;
}

// ---------------- CSR build ----------------
__global__ void zero_int_kernel(int* __restrict__ p, int n) {
    int i = blockIdx.x * blockDim.x + threadIdx.x;
    if (i < n) p[i] = 0;
}

__global__ void deg_kernel(const int* __restrict__ dst, int* __restrict__ deg) {
    int e = blockIdx.x * blockDim.x + threadIdx.x;
    if (e < NE) atomicAdd(deg + dst[e], 1);
}

__global__ void partial_kernel(const int* __restrict__ deg, int* __restrict__ part) {
    __shared__ int sh[SCAN_B];
    int b = blockIdx.x;
    int t = threadIdx.x;
    int i = b * SCAN_B + t;
    sh[t] = (i < NN) ? deg[i] : 0;
    __syncthreads();
    for (int off = SCAN_B / 2; off > 0; off >>= 1) {
        if (t < off) sh[t] += sh[t + off];
        __syncthreads();
    }
    if (t == 0) part[b] = sh[0];
}

__global__ void scanpart_kernel(int* __restrict__ part, int* __restrict__ rowptr) {
    __shared__ int sh[512];
    int t = threadIdx.x;
    sh[t] = (t < SCAN_NB) ? part[t] : 0;
    __syncthreads();
    // inclusive Hillis-Steele
    for (int off = 1; off < 512; off <<= 1) {
        int v = (t >= off) ? sh[t - off] : 0;
        __syncthreads();
        sh[t] += v;
        __syncthreads();
    }
    // exclusive
    if (t < SCAN_NB) part[t] = (t == 0) ? 0 : sh[t - 1];
    if (t == 0) rowptr[NN] = NE;
}

__global__ void rowptr_kernel(const int* __restrict__ deg, const int* __restrict__ part,
                              int* __restrict__ rowptr, int* __restrict__ cursor) {
    __shared__ int sh[SCAN_B];
    int b = blockIdx.x;
    int t = threadIdx.x;
    int i = b * SCAN_B + t;
    sh[t] = (i < NN) ? deg[i] : 0;
    __syncthreads();
    for (int off = 1; off < SCAN_B; off <<= 1) {
        int v = (t >= off) ? sh[t - off] : 0;
        __syncthreads();
        sh[t] += v;
        __syncthreads();
    }
    if (i < NN) {
        int excl = part[b] + ((t == 0) ? 0 : sh[t - 1]);
        rowptr[i] = excl;
        cursor[i] = excl;
    }
}

__global__ void fill_kernel(const int* __restrict__ src, const int* __restrict__ dst,
                            int* __restrict__ cursor, int* __restrict__ col) {
    int e = blockIdx.x * blockDim.x + threadIdx.x;
    if (e < NE) {
        int p = atomicAdd(cursor + dst[e], 1);
        col[p] = src[e];
    }
}

// ---------------- kernel: per-node gather  agg[i] = x[i] + sum_{j in N(i)} x[j] ----------------
__global__ __launch_bounds__(256)
void gather_kernel(const float* __restrict__ x, const int* __restrict__ rowptr,
                   const int* __restrict__ col, float* __restrict__ agg) {
    int node = blockIdx.x * 8 + (threadIdx.x >> 5);
    if (node >= NN) return;
    int lane = threadIdx.x & 31;
    int beg = rowptr[node];
    int end = rowptr[node + 1];
    const float* xr = x + (size_t)lane * 4;
    float4 acc = *(const float4*)(x + (size_t)node * H + lane * 4);
    int j = beg;
    for (; j + 1 < end; j += 2) {
        int s0 = col[j];
        int s1 = col[j + 1];
        float4 a = *(const float4*)(xr + (size_t)s0 * H);
        float4 b = *(const float4*)(xr + (size_t)s1 * H);
        acc.x += a.x + b.x; acc.y += a.y + b.y;
        acc.z += a.z + b.z; acc.w += a.w + b.w;
    }
    if (j < end) {
        int s0 = col[j];
        float4 a = *(const float4*)(xr + (size_t)s0 * H);
        acc.x += a.x; acc.y += a.y; acc.z += a.z; acc.w += a.w;
    }
    *(float4*)(agg + (size_t)node * H + lane * 4) = acc;
}

// ---------------- kernel: build E = [embed_tab[z], pos@W_pos + b_pos] ----------------
__global__ void build_embed_kernel(const int* __restrict__ z, const float* __restrict__ pos,
                                   const float* __restrict__ tab, const float* __restrict__ Wp,
                                   const float* __restrict__ bp, float* __restrict__ E) {
    int gid = blockIdx.x * blockDim.x + threadIdx.x;
    if (gid >= NN * 64) return;
    int i = gid >> 6;
    int j = gid & 63;
    if (j < 32) {
        int c = j * 4;
        float4 v = *(const float4*)(tab + (size_t)z[i] * H + c);
        *(float4*)(E + (size_t)i * 256 + c) = v;
    } else {
        int c = (j - 32) * 4;
        float p0 = pos[i * 3 + 0], p1 = pos[i * 3 + 1], p2 = pos[i * 3 + 2];
        float4 v;
        v.x = p0 * Wp[0 * H + c + 0] + p1 * Wp[1 * H + c + 0] + p2 * Wp[2 * H + c + 0] + bp[c + 0];
        v.y = p0 * Wp[0 * H + c + 1] + p1 * Wp[1 * H + c + 1] + p2 * Wp[2 * H + c + 1] + bp[c + 1];
        v.z = p0 * Wp[0 * H + c + 2] + p1 * Wp[1 * H + c + 2] + p2 * Wp[2 * H + c + 2] + bp[c + 2];
        v.w = p0 * Wp[0 * H + c + 3] + p1 * Wp[1 * H + c + 3] + p2 * Wp[2 * H + c + 3] + bp[c + 3];
        *(float4*)(E + (size_t)i * 256 + 128 + c) = v;
    }
}

// ---------------- kernel: fp32 GEMM  C[M,128] = act(A @ W[K,128] + b) ----------------
// BM=128, BN=128, BK=16, 256 threads, 8x8 per-thread microtile.
template<int K, bool RELU>
__global__ __launch_bounds__(256)
void gemm128_kernel(const float* __restrict__ A,
                    const float* __restrict__ W, const float* __restrict__ bias,
                    float* __restrict__ C, int M) {
    __shared__ float As[16][132];
    __shared__ float Ws[16][128];

    int t = threadIdx.x;
    int m0 = blockIdx.x * 128;
    int tx = t & 15;
    int ty = t >> 4;

    float acc[8][8];
#pragma unroll
    for (int i = 0; i < 8; i++)
#pragma unroll
        for (int j = 0; j < 8; j++) acc[i][j] = 0.f;

    for (int k0 = 0; k0 < K; k0 += 16) {
#pragma unroll
        for (int it = 0; it < 2; it++) {
            int idx = t + it * 256;
            int row = idx >> 2;
            int kq  = (idx & 3) * 4;
            int grow = m0 + row;
            float4 a = make_float4(0.f, 0.f, 0.f, 0.f);
            if (grow < M) a = *(const float4*)(A + (size_t)grow * K + k0 + kq);
            As[kq + 0][row] = a.x;
            As[kq + 1][row] = a.y;
            As[kq + 2][row] = a.z;
            As[kq + 3][row] = a.w;
            int wr = idx >> 5;
            int wc = (idx & 31) * 4;
            *(float4*)&Ws[wr][wc] = *(const float4*)(W + (size_t)(k0 + wr) * 128 + wc);
        }
        __syncthreads();

#pragma unroll
        for (int kk = 0; kk < 16; kk++) {
            float a[8], w[8];
            *(float4*)&a[0] = *(const float4*)&As[kk][ty * 4];
            *(float4*)&a[4] = *(const float4*)&As[kk][ty * 4 + 64];
            *(float4*)&w[0] = *(const float4*)&Ws[kk][tx * 4];
            *(float4*)&w[4] = *(const float4*)&Ws[kk][tx * 4 + 64];
#pragma unroll
            for (int i = 0; i < 8; i++)
#pragma unroll
                for (int j = 0; j < 8; j++)
                    acc[i][j] = fmaf(a[i], w[j], acc[i][j]);
        }
        __syncthreads();
    }

#pragma unroll
    for (int i = 0; i < 8; i++) {
        int row = m0 + ty * 4 + (i & 3) + ((i >> 2) << 6);
        if (row >= M) continue;
#pragma unroll
        for (int jh = 0; jh < 2; jh++) {
            int col = tx * 4 + jh * 64;
            float4 v;
            v.x = acc[i][jh * 4 + 0] + bias[col + 0];
            v.y = acc[i][jh * 4 + 1] + bias[col + 1];
            v.z = acc[i][jh * 4 + 2] + bias[col + 2];
            v.w = acc[i][jh * 4 + 3] + bias[col + 3];
            if (RELU) {
                v.x = fmaxf(v.x, 0.f); v.y = fmaxf(v.y, 0.f);
                v.z = fmaxf(v.z, 0.f); v.w = fmaxf(v.w, 0.f);
            }
            *(float4*)(C + (size_t)row * 128 + col) = v;
        }
    }
}

// ---------------- kernel: per-graph sum pooling (batch is sorted) ----------------
__global__ void pool_kernel(const float* __restrict__ x, const int* __restrict__ batch,
                            float* __restrict__ pool) {
    int g = blockIdx.x;
    int f = threadIdx.x;
    __shared__ int slo, shi;
    if (f == 0) {
        slo = lbound(batch, NN, g);
        shi = lbound(batch, NN, g + 1);
    }
    __syncthreads();
    float s = 0.f;
    for (int i = slo; i < shi; i++) s += x[(size_t)i * H + f];
    pool[(size_t)g * H + f] = s;
}

// ---------------- kernel: 4 heads, Linear-ReLU-Linear over pooled features ----------------
__global__ void heads_kernel(const float* __restrict__ pool, const float* __restrict__ W1,
                             const float* __restrict__ b1, const float* __restrict__ W2,
                             const float* __restrict__ b2, float* __restrict__ hout) {
    int k  = blockIdx.x;
    int gc = blockIdx.y;
    int f  = threadIdx.x;
    __shared__ float rows[16][128];
    __shared__ float red[16][128];
    int g0 = gc * 16;
#pragma unroll
    for (int g = 0; g < 16; g++) rows[g][f] = pool[(size_t)(g0 + g) * H + f];
    __syncthreads();

    const float* W1k = W1 + (size_t)k * H * H;
    float acc[16];
#pragma unroll
    for (int g = 0; g < 16; g++) acc[g] = 0.f;
    for (int h = 0; h < 128; h++) {
        float w = W1k[(size_t)h * H + f];
#pragma unroll
        for (int g = 0; g < 16; g++) acc[g] = fmaf(rows[g][h], w, acc[g]);
    }
    float bb = b1[k * H + f];
    float w2 = W2[k * H + f];
#pragma unroll
    for (int g = 0; g < 16; g++) red[g][f] = fmaxf(acc[g] + bb, 0.f) * w2;
    __syncthreads();
    if (f < 16) {
        float s = 0.f;
        for (int h = 0; h < 128; h++) s += red[f][h];
        hout[k * NG + g0 + f] = s + b2[k];
    }
}

// ---------------- kernel: evidential epilogue ----------------
__global__ void final_kernel(const float* __restrict__ ho, float* __restrict__ out) {
    int g = blockIdx.x * blockDim.x + threadIdx.x;
    if (g >= NG) return;
    float o0 = ho[0 * NG + g];
    float o1 = ho[1 * NG + g];
    float o2 = ho[2 * NG + g];
    float o3 = ho[3 * NG + g];
    float alpha = fmaxf(softplusf(o0) + 1.f, 1.f + 1e-4f);
    float beta  = softplusf(o1);
    float nu    = softplusf(o2);
    float am1   = alpha - 1.f;
    out[0 * NG + g] = o3;
    out[1 * NG + g] = beta / am1;
    out[2 * NG + g] = beta / (am1 * nu);
    out[3 * NG + g] = nu;
    out[4 * NG + g] = alpha;
    out[5 * NG + g] = beta;
}

// ---------------- launch ----------------
extern "C" void kernel_launch(void* const* d_in, const int* in_sizes, int n_in,
                              void* d_out, int out_size) {
    const int*   z      = (const int*)  d_in[0];
    const float* pos    = (const float*)d_in[1];
    const int*   batch  = (const int*)  d_in[2];
    const int*   eidx   = (const int*)  d_in[3];   // [2, NE]: row0 src, row1 dst
    const float* tab    = (const float*)d_in[4];
    const float* Wp     = (const float*)d_in[5];
    const float* bp     = (const float*)d_in[6];
    const float* Wcomb  = (const float*)d_in[7];
    const float* bcomb  = (const float*)d_in[8];
    const float* gW1    = (const float*)d_in[9];
    const float* gb1    = (const float*)d_in[10];
    const float* gW2    = (const float*)d_in[11];
    const float* gb2    = (const float*)d_in[12];
    const float* hW1    = (const float*)d_in[13];
    const float* hb1    = (const float*)d_in[14];
    const float* hW2    = (const float*)d_in[15];
    const float* hb2    = (const float*)d_in[16];
    float* out = (float*)d_out;

    float *E, *x, *y, *agg, *pool, *ho;
    int *deg, *rowptr, *cursor, *col, *part;
    cudaGetSymbolAddress((void**)&E,      g_E);
    cudaGetSymbolAddress((void**)&x,      g_x);
    cudaGetSymbolAddress((void**)&y,      g_y);
    cudaGetSymbolAddress((void**)&agg,    g_agg);
    cudaGetSymbolAddress((void**)&pool,   g_pool);
    cudaGetSymbolAddress((void**)&ho,     g_ho);
    cudaGetSymbolAddress((void**)&deg,    g_deg);
    cudaGetSymbolAddress((void**)&rowptr, g_rowptr);
    cudaGetSymbolAddress((void**)&cursor, g_cursor);
    cudaGetSymbolAddress((void**)&col,    g_col);
    cudaGetSymbolAddress((void**)&part,   g_part);

    const int gemm_grid = (NN + 127) / 128;   // 391
    const int* src = eidx;
    const int* dst = eidx + NE;

    // --- CSR build (once; edge_index is reused by all 4 layers) ---
    zero_int_kernel<<<(NN + 255) / 256, 256>>>(deg, NN);
    deg_kernel<<<(NE + 255) / 256, 256>>>(dst, deg);
    partial_kernel<<<SCAN_NB, SCAN_B>>>(deg, part);
    scanpart_kernel<<<1, 512>>>(part, rowptr);
    rowptr_kernel<<<SCAN_NB, SCAN_B>>>(deg, part, rowptr, cursor);
    fill_kernel<<<(NE + 255) / 256, 256>>>(src, dst, cursor, col);

    // --- initial embedding + combine MLP ---
    build_embed_kernel<<<(NN * 64 + 255) / 256, 256>>>(z, pos, tab, Wp, bp, E);
    gemm128_kernel<256, true><<<gemm_grid, 256>>>(E, Wcomb, bcomb, x, NN);

    // --- GIN layers (gather includes the self term: agg = x + sum_neighbors) ---
    for (int l = 0; l < NL; l++) {
        gather_kernel<<<(NN + 7) / 8, 256>>>(x, rowptr, col, agg);
        gemm128_kernel<128, true><<<gemm_grid, 256>>>(
            agg, gW1 + (size_t)l * H * H, gb1 + (size_t)l * H, y, NN);
        if (l < NL - 1) {
            gemm128_kernel<128, true><<<gemm_grid, 256>>>(
                y, gW2 + (size_t)l * H * H, gb2 + (size_t)l * H, x, NN);
        } else {
            gemm128_kernel<128, false><<<gemm_grid, 256>>>(
                y, gW2 + (size_t)l * H * H, gb2 + (size_t)l * H, x, NN);
        }
    }

    // --- pooling / heads / epilogue ---
    pool_kernel<<<NG, 128>>>(x, batch, pool);
    heads_kernel<<<dim3(4, 32), 128>>>(pool, hW1, hb1, hW2, hb2, ho);
    final_kernel<<<2, 256>>>(ho, out);
}

// round 6
// speedup vs baseline: 1.4454x; 1.0297x over previous
#include <cuda_runtime.h>
#include <cuda_bf16.h>
#include <cstdint>

#define NN 50000
#define NE 800000
#define NG 512
#define H  128
#define NL 4

#define SCAN_B  128
#define SCAN_NB ((NN + SCAN_B - 1) / SCAN_B)   // 391

// padded bf16 tile row length (elements) to keep ldmatrix bank-conflict free
#define LDK 136
#define PLANE (128 * LDK)            // 17408 elements per plane

// ---------------- device scratch (static, no allocations) ----------------
__device__ float g_E  [(size_t)NN * 2 * H];   // E0 = atom embed, E1 = pos embed
__device__ float g_x  [(size_t)NN * H];
__device__ float g_y  [(size_t)NN * H];
__device__ float g_agg[(size_t)NN * H];
__device__ float g_pool[(size_t)NG * H];
__device__ float g_ho [4 * NG];
// pre-split weights: 10 matrices x (hi plane + lo plane), transposed to [n][k]
// K-major with rows padded to LDK. uint4 for 16B alignment.
__device__ uint4 g_wt[(size_t)10 * 2 * PLANE * 2 / 16];
// CSR scratch
__device__ int g_deg   [NN];
__device__ int g_rowptr[NN + 1];
__device__ int g_cursor[NN];
__device__ int g_col   [NE];
__device__ int g_part  [SCAN_NB];

// ---------------- helpers ----------------
__device__ __forceinline__ uint32_t smem_to_u32(const void* p) {
    uint32_t a;
    asm("{ .reg .u64 t; cvta.to.shared.u64 t, %1; cvt.u32.u64 %0, t; }" : "=r"(a) : "l"(p));
    return a;
}
__device__ __forceinline__ uint32_t pack_bf16x2(float lo_elem, float hi_elem) {
    uint32_t r;
    asm("cvt.rn.bf16x2.f32 %0, %1, %2;" : "=r"(r) : "f"(hi_elem), "f"(lo_elem));
    return r;
}
__device__ __forceinline__ void ldsm_x4(uint32_t addr, uint32_t& r0, uint32_t& r1,
                                        uint32_t& r2, uint32_t& r3) {
    asm volatile("ldmatrix.sync.aligned.m8n8.x4.shared.b16 {%0,%1,%2,%3}, [%4];"
                 : "=r"(r0), "=r"(r1), "=r"(r2), "=r"(r3) : "r"(addr));
}
__device__ __forceinline__ void ldsm_x2(uint32_t addr, uint32_t& r0, uint32_t& r1) {
    asm volatile("ldmatrix.sync.aligned.m8n8.x2.shared.b16 {%0,%1}, [%2];"
                 : "=r"(r0), "=r"(r1) : "r"(addr));
}
__device__ __forceinline__ void mma16816(float* c, const uint32_t* a, const uint32_t* b) {
    asm volatile("mma.sync.aligned.m16n8k16.row.col.f32.bf16.bf16.f32 "
                 "{%0,%1,%2,%3}, {%4,%5,%6,%7}, {%8,%9}, {%0,%1,%2,%3};"
                 : "+f"(c[0]), "+f"(c[1]), "+f"(c[2]), "+f"(c[3])
                 : "r"(a[0]), "r"(a[1]), "r"(a[2]), "r"(a[3]), "r"(b[0]), "r"(b[1]));
}
__device__ __forceinline__ float softplusf(float x) {
    return fmaxf(x, 0.f) + log1pf(expf(-fabsf(x)));
}
__device__ __forceinline__ int lbound(const int* __restrict__ a, int n, int v) {
    int lo = 0, hi = n;
    while (lo < hi) { int m = (lo + hi) >> 1; if (a[m] < v) lo = m + 1; else hi = m; }
    return lo;
}

// ---------------- CSR build ----------------
__global__ void zero_int_kernel(int* __restrict__ p, int n) {
    int i = blockIdx.x * blockDim.x + threadIdx.x;
    if (i < n) p[i] = 0;
}
__global__ void deg_kernel(const int* __restrict__ dst, int* __restrict__ deg) {
    int e = blockIdx.x * blockDim.x + threadIdx.x;
    if (e < NE) atomicAdd(deg + dst[e], 1);
}
__global__ void partial_kernel(const int* __restrict__ deg, int* __restrict__ part) {
    __shared__ int sh[SCAN_B];
    int b = blockIdx.x, t = threadIdx.x, i = b * SCAN_B + t;
    sh[t] = (i < NN) ? deg[i] : 0;
    __syncthreads();
    for (int off = SCAN_B / 2; off > 0; off >>= 1) {
        if (t < off) sh[t] += sh[t + off];
        __syncthreads();
    }
    if (t == 0) part[b] = sh[0];
}
__global__ void scanpart_kernel(int* __restrict__ part, int* __restrict__ rowptr) {
    __shared__ int sh[512];
    int t = threadIdx.x;
    sh[t] = (t < SCAN_NB) ? part[t] : 0;
    __syncthreads();
    for (int off = 1; off < 512; off <<= 1) {
        int v = (t >= off) ? sh[t - off] : 0;
        __syncthreads();
        sh[t] += v;
        __syncthreads();
    }
    if (t < SCAN_NB) part[t] = (t == 0) ? 0 : sh[t - 1];
    if (t == 0) rowptr[NN] = NE;
}
__global__ void rowptr_kernel(const int* __restrict__ deg, const int* __restrict__ part,
                              int* __restrict__ rowptr, int* __restrict__ cursor) {
    __shared__ int sh[SCAN_B];
    int b = blockIdx.x, t = threadIdx.x, i = b * SCAN_B + t;
    sh[t] = (i < NN) ? deg[i] : 0;
    __syncthreads();
    for (int off = 1; off < SCAN_B; off <<= 1) {
        int v = (t >= off) ? sh[t - off] : 0;
        __syncthreads();
        sh[t] += v;
        __syncthreads();
    }
    if (i < NN) {
        int excl = part[b] + ((t == 0) ? 0 : sh[t - 1]);
        rowptr[i] = excl;
        cursor[i] = excl;
    }
}
__global__ void fill_kernel(const int* __restrict__ src, const int* __restrict__ dst,
                            int* __restrict__ cursor, int* __restrict__ col) {
    int e = blockIdx.x * blockDim.x + threadIdx.x;
    if (e < NE) {
        int p = atomicAdd(cursor + dst[e], 1);
        col[p] = src[e];
    }
}

// ---------------- gather: agg[i] = x[i] + sum_{j in N(i)} x[j] ----------------
__global__ __launch_bounds__(256)
void gather_kernel(const float* __restrict__ x, const int* __restrict__ rowptr,
                   const int* __restrict__ col, float* __restrict__ agg) {
    int node = blockIdx.x * 8 + (threadIdx.x >> 5);
    if (node >= NN) return;
    int lane = threadIdx.x & 31;
    int beg = rowptr[node];
    int end = rowptr[node + 1];
    const float* xr = x + (size_t)lane * 4;
    float4 acc = *(const float4*)(x + (size_t)node * H + lane * 4);
    int j = beg;
    for (; j + 1 < end; j += 2) {
        int s0 = col[j], s1 = col[j + 1];
        float4 a = *(const float4*)(xr + (size_t)s0 * H);
        float4 b = *(const float4*)(xr + (size_t)s1 * H);
        acc.x += a.x + b.x; acc.y += a.y + b.y;
        acc.z += a.z + b.z; acc.w += a.w + b.w;
    }
    if (j < end) {
        int s0 = col[j];
        float4 a = *(const float4*)(xr + (size_t)s0 * H);
        acc.x += a.x; acc.y += a.y; acc.z += a.z; acc.w += a.w;
    }
    *(float4*)(agg + (size_t)node * H + lane * 4) = acc;
}

// ---------------- embed: E0 = embed_tab[z], E1 = pos @ W_pos + b_pos ----------------
__global__ void build_embed_kernel(const int* __restrict__ z, const float* __restrict__ pos,
                                   const float* __restrict__ tab, const float* __restrict__ Wp,
                                   const float* __restrict__ bp,
                                   float* __restrict__ E0, float* __restrict__ E1) {
    int gid = blockIdx.x * blockDim.x + threadIdx.x;
    if (gid >= NN * 64) return;
    int i = gid >> 6;
    int j = gid & 63;
    if (j < 32) {
        int c = j * 4;
        *(float4*)(E0 + (size_t)i * H + c) = *(const float4*)(tab + (size_t)z[i] * H + c);
    } else {
        int c = (j - 32) * 4;
        float p0 = pos[i * 3 + 0], p1 = pos[i * 3 + 1], p2 = pos[i * 3 + 2];
        float4 v;
        v.x = p0 * Wp[0 * H + c + 0] + p1 * Wp[1 * H + c + 0] + p2 * Wp[2 * H + c + 0] + bp[c + 0];
        v.y = p0 * Wp[0 * H + c + 1] + p1 * Wp[1 * H + c + 1] + p2 * Wp[2 * H + c + 1] + bp[c + 1];
        v.z = p0 * Wp[0 * H + c + 2] + p1 * Wp[1 * H + c + 2] + p2 * Wp[2 * H + c + 2] + bp[c + 2];
        v.w = p0 * Wp[0 * H + c + 3] + p1 * Wp[1 * H + c + 3] + p2 * Wp[2 * H + c + 3] + bp[c + 3];
        *(float4*)(E1 + (size_t)i * H + c) = v;
    }
}

// ---------------- weight prep: transpose + bf16 hi/lo split, padded [n][LDK] ----------------
// mat 0..1: Wcomb halves (rows 0..127 / 128..255); 2..5: gin_W1[l]; 6..9: gin_W2[l]
__global__ void prep_weights_kernel(const float* __restrict__ Wcomb, const float* __restrict__ gW1,
                                    const float* __restrict__ gW2, __nv_bfloat16* __restrict__ wt) {
    int gid = blockIdx.x * blockDim.x + threadIdx.x;
    if (gid >= 10 * 16384) return;
    int mat = gid >> 14;
    int k   = (gid >> 7) & 127;
    int n   = gid & 127;
    const float* Wsrc = (mat < 2) ? Wcomb + (size_t)mat * 16384
                      : (mat < 6) ? gW1 + (size_t)(mat - 2) * 16384
                                  : gW2 + (size_t)(mat - 6) * 16384;
    float v = Wsrc[(size_t)k * 128 + n];       // B[n][k] = W[k][n]
    float h = __bfloat162float(__float2bfloat16(v));
    float l = v - h;
    __nv_bfloat16* base = wt + (size_t)mat * 2 * PLANE;
    base[(size_t)n * LDK + k]         = __float2bfloat16(h);
    base[PLANE + (size_t)n * LDK + k] = __float2bfloat16(l);
}

// ---------------- HMMA GEMM: C[M,128] = act(A[M,128] @ W + bias (+ Cin)) ----------------
// split precision: A=Ah+Al, B=Bh+Bl bf16; C = AhBh + AhBl + AlBh (fp32 accum)
#define SM_A_HI 0
#define SM_A_LO (PLANE * 2)
#define SM_B_HI (PLANE * 4)
#define SM_B_LO (PLANE * 6)
#define GEMM_SMEM (PLANE * 8)       // 139264 bytes

template<bool RELU, bool BIAS, bool ADDC>
__global__ __launch_bounds__(256)
void gemm_tc_kernel(const float* __restrict__ A, const uint4* __restrict__ Bt,
                    const float* __restrict__ bias, const float* __restrict__ Cin,
                    float* __restrict__ C, int M) {
    extern __shared__ char smem[];
    uint32_t sb = smem_to_u32(smem);
    int t = threadIdx.x, wid = t >> 5, lane = t & 31;
    int m0 = blockIdx.x * 128;

    // copy pre-split B (hi+lo, 69632 B raw)
    {
        uint4* dv = (uint4*)(smem + SM_B_HI);
        for (int i = t; i < GEMM_SMEM / 32; i += 256) dv[i] = Bt[i];   // 4352 uint4
    }
    // load + split-convert A tile [128,128] fp32 -> hi/lo bf16 in [128][LDK]
    {
        int r = t >> 1, c0 = (t & 1) << 6;
        int gr = m0 + r;
        const float4* Arow = (const float4*)(A + (size_t)gr * 128 + c0);
        uint32_t eoff = (uint32_t)r * LDK + c0;
#pragma unroll
        for (int q = 0; q < 16; q += 2) {
            float4 va = (gr < M) ? Arow[q]     : make_float4(0.f, 0.f, 0.f, 0.f);
            float4 vb = (gr < M) ? Arow[q + 1] : make_float4(0.f, 0.f, 0.f, 0.f);
            float h0 = __bfloat162float(__float2bfloat16(va.x));
            float h1 = __bfloat162float(__float2bfloat16(va.y));
            float h2 = __bfloat162float(__float2bfloat16(va.z));
            float h3 = __bfloat162float(__float2bfloat16(va.w));
            float h4 = __bfloat162float(__float2bfloat16(vb.x));
            float h5 = __bfloat162float(__float2bfloat16(vb.y));
            float h6 = __bfloat162float(__float2bfloat16(vb.z));
            float h7 = __bfloat162float(__float2bfloat16(vb.w));
            uint4 hi4, lo4;
            hi4.x = pack_bf16x2(h0, h1);               hi4.y = pack_bf16x2(h2, h3);
            hi4.z = pack_bf16x2(h4, h5);               hi4.w = pack_bf16x2(h6, h7);
            lo4.x = pack_bf16x2(va.x - h0, va.y - h1); lo4.y = pack_bf16x2(va.z - h2, va.w - h3);
            lo4.z = pack_bf16x2(vb.x - h4, vb.y - h5); lo4.w = pack_bf16x2(vb.z - h6, vb.w - h7);
            *(uint4*)(smem + SM_A_HI + (eoff + q * 4) * 2) = hi4;
            *(uint4*)(smem + SM_A_LO + (eoff + q * 4) * 2) = lo4;
        }
    }
    __syncthreads();

    // warp tile: 32 rows x 64 cols
    int mrow0 = (wid >> 1) * 32;
    int ncol0 = (wid & 1) * 64;

    float acc[2][8][4];
#pragma unroll
    for (int mi = 0; mi < 2; mi++)
#pragma unroll
        for (int nf = 0; nf < 8; nf++)
#pragma unroll
            for (int q = 0; q < 4; q++) acc[mi][nf][q] = 0.f;

    // ldmatrix lane addressing
    int la = lane & 15;
    uint32_t aoffA = ((uint32_t)(mrow0 + la) * LDK + (lane >> 4) * 8) * 2;      // + mi*16*LDK*2
    uint32_t aAh = sb + SM_A_HI + aoffA;
    uint32_t aAl = sb + SM_A_LO + aoffA;
    uint32_t boffB = ((uint32_t)(ncol0 + (la & 7)) * LDK + ((la >> 3) & 1) * 8) * 2;  // + nf*8*LDK*2
    uint32_t aBh = sb + SM_B_HI + boffB;
    uint32_t aBl = sb + SM_B_LO + boffB;

#pragma unroll
    for (int kk = 0; kk < 8; kk++) {
        uint32_t ko = kk * 32;    // 16 elements * 2B
        uint32_t ah[2][4], al[2][4];
#pragma unroll
        for (int mi = 0; mi < 2; mi++) {
            ldsm_x4(aAh + mi * (16 * LDK * 2) + ko, ah[mi][0], ah[mi][1], ah[mi][2], ah[mi][3]);
            ldsm_x4(aAl + mi * (16 * LDK * 2) + ko, al[mi][0], al[mi][1], al[mi][2], al[mi][3]);
        }
#pragma unroll
        for (int nf = 0; nf < 8; nf++) {
            uint32_t bh[2], bl[2];
            ldsm_x2(aBh + nf * (8 * LDK * 2) + ko, bh[0], bh[1]);
            ldsm_x2(aBl + nf * (8 * LDK * 2) + ko, bl[0], bl[1]);
#pragma unroll
            for (int mi = 0; mi < 2; mi++) {
                mma16816(acc[mi][nf], ah[mi], bh);
                mma16816(acc[mi][nf], ah[mi], bl);
                mma16816(acc[mi][nf], al[mi], bh);
            }
        }
    }

    // epilogue: c0,c1 -> (row, col..col+1); c2,c3 -> (row+8, col..col+1)
    int rbase = mrow0 + (lane >> 2);
    int cbase = ncol0 + (lane & 3) * 2;
#pragma unroll
    for (int mi = 0; mi < 2; mi++) {
#pragma unroll
        for (int half = 0; half < 2; half++) {
            int row = rbase + mi * 16 + half * 8;
            int m = m0 + row;
            if (m >= M) continue;
#pragma unroll
            for (int nf = 0; nf < 8; nf++) {
                int colc = cbase + nf * 8;
                float2 v;
                v.x = acc[mi][nf][half * 2 + 0];
                v.y = acc[mi][nf][half * 2 + 1];
                if (BIAS) {
                    float2 b2 = *(const float2*)(bias + colc);
                    v.x += b2.x; v.y += b2.y;
                }
                if (ADDC) {
                    float2 c2 = *(const float2*)(Cin + (size_t)m * 128 + colc);
                    v.x += c2.x; v.y += c2.y;
                }
                if (RELU) { v.x = fmaxf(v.x, 0.f); v.y = fmaxf(v.y, 0.f); }
                *(float2*)(C + (size_t)m * 128 + colc) = v;
            }
        }
    }
}

// ---------------- pooling / heads / epilogue ----------------
__global__ void pool_kernel(const float* __restrict__ x, const int* __restrict__ batch,
                            float* __restrict__ pool) {
    int g = blockIdx.x, f = threadIdx.x;
    __shared__ int slo, shi;
    if (f == 0) { slo = lbound(batch, NN, g); shi = lbound(batch, NN, g + 1); }
    __syncthreads();
    float s = 0.f;
    for (int i = slo; i < shi; i++) s += x[(size_t)i * H + f];
    pool[(size_t)g * H + f] = s;
}

__global__ void heads_kernel(const float* __restrict__ pool, const float* __restrict__ W1,
                             const float* __restrict__ b1, const float* __restrict__ W2,
                             const float* __restrict__ b2, float* __restrict__ hout) {
    int k = blockIdx.x, gc = blockIdx.y, f = threadIdx.x;
    __shared__ float rows[16][128];
    __shared__ float red[16][128];
    int g0 = gc * 16;
#pragma unroll
    for (int g = 0; g < 16; g++) rows[g][f] = pool[(size_t)(g0 + g) * H + f];
    __syncthreads();
    const float* W1k = W1 + (size_t)k * H * H;
    float acc[16];
#pragma unroll
    for (int g = 0; g < 16; g++) acc[g] = 0.f;
    for (int h = 0; h < 128; h++) {
        float w = W1k[(size_t)h * H + f];
#pragma unroll
        for (int g = 0; g < 16; g++) acc[g] = fmaf(rows[g][h], w, acc[g]);
    }
    float bb = b1[k * H + f];
    float w2 = W2[k * H + f];
#pragma unroll
    for (int g = 0; g < 16; g++) red[g][f] = fmaxf(acc[g] + bb, 0.f) * w2;
    __syncthreads();
    if (f < 16) {
        float s = 0.f;
        for (int h = 0; h < 128; h++) s += red[f][h];
        hout[k * NG + g0 + f] = s + b2[k];
    }
}

__global__ void final_kernel(const float* __restrict__ ho, float* __restrict__ out) {
    int g = blockIdx.x * blockDim.x + threadIdx.x;
    if (g >= NG) return;
    float o0 = ho[0 * NG + g], o1 = ho[1 * NG + g];
    float o2 = ho[2 * NG + g], o3 = ho[3 * NG + g];
    float alpha = fmaxf(softplusf(o0) + 1.f, 1.f + 1e-4f);
    float beta  = softplusf(o1);
    float nu    = softplusf(o2);
    float am1   = alpha - 1.f;
    out[0 * NG + g] = o3;
    out[1 * NG + g] = beta / am1;
    out[2 * NG + g] = beta / (am1 * nu);
    out[3 * NG + g] = nu;
    out[4 * NG + g] = alpha;
    out[5 * NG + g] = beta;
}

// ---------------- launch ----------------
extern "C" void kernel_launch(void* const* d_in, const int* in_sizes, int n_in,
                              void* d_out, int out_size) {
    const int*   z      = (const int*)  d_in[0];
    const float* pos    = (const float*)d_in[1];
    const int*   batch  = (const int*)  d_in[2];
    const int*   eidx   = (const int*)  d_in[3];
    const float* tab    = (const float*)d_in[4];
    const float* Wp     = (const float*)d_in[5];
    const float* bp     = (const float*)d_in[6];
    const float* Wcomb  = (const float*)d_in[7];
    const float* bcomb  = (const float*)d_in[8];
    const float* gW1    = (const float*)d_in[9];
    const float* gb1    = (const float*)d_in[10];
    const float* gW2    = (const float*)d_in[11];
    const float* gb2    = (const float*)d_in[12];
    const float* hW1    = (const float*)d_in[13];
    const float* hb1    = (const float*)d_in[14];
    const float* hW2    = (const float*)d_in[15];
    const float* hb2    = (const float*)d_in[16];
    float* out = (float*)d_out;

    float *E, *x, *y, *agg, *pool, *ho;
    uint4* wt;
    int *deg, *rowptr, *cursor, *col, *part;
    cudaGetSymbolAddress((void**)&E,      g_E);
    cudaGetSymbolAddress((void**)&x,      g_x);
    cudaGetSymbolAddress((void**)&y,      g_y);
    cudaGetSymbolAddress((void**)&agg,    g_agg);
    cudaGetSymbolAddress((void**)&pool,   g_pool);
    cudaGetSymbolAddress((void**)&ho,     g_ho);
    cudaGetSymbolAddress((void**)&wt,     g_wt);
    cudaGetSymbolAddress((void**)&deg,    g_deg);
    cudaGetSymbolAddress((void**)&rowptr, g_rowptr);
    cudaGetSymbolAddress((void**)&cursor, g_cursor);
    cudaGetSymbolAddress((void**)&col,    g_col);
    cudaGetSymbolAddress((void**)&part,   g_part);

    float* E0 = E;
    float* E1 = E + (size_t)NN * H;

    cudaFuncSetAttribute(gemm_tc_kernel<false, false, false>, cudaFuncAttributeMaxDynamicSharedMemorySize, GEMM_SMEM);
    cudaFuncSetAttribute(gemm_tc_kernel<true,  true,  true >, cudaFuncAttributeMaxDynamicSharedMemorySize, GEMM_SMEM);
    cudaFuncSetAttribute(gemm_tc_kernel<true,  true,  false>, cudaFuncAttributeMaxDynamicSharedMemorySize, GEMM_SMEM);
    cudaFuncSetAttribute(gemm_tc_kernel<false, true,  false>, cudaFuncAttributeMaxDynamicSharedMemorySize, GEMM_SMEM);

    const int gemm_grid = (NN + 127) / 128;   // 391
    const int* src = eidx;
    const int* dst = eidx + NE;

    // per-matrix stride in uint4 units (2 planes * PLANE elements * 2B / 16)
    const size_t mat_u4 = (size_t)2 * PLANE * 2 / 16;   // 4352

    // --- CSR build (edge_index reused by all layers) ---
    zero_int_kernel<<<(NN + 255) / 256, 256>>>(deg, NN);
    deg_kernel<<<(NE + 255) / 256, 256>>>(dst, deg);
    partial_kernel<<<SCAN_NB, SCAN_B>>>(deg, part);
    scanpart_kernel<<<1, 512>>>(part, rowptr);
    rowptr_kernel<<<SCAN_NB, SCAN_B>>>(deg, part, rowptr, cursor);
    fill_kernel<<<(NE + 255) / 256, 256>>>(src, dst, cursor, col);

    // --- weight prep ---
    prep_weights_kernel<<<(10 * 16384 + 255) / 256, 256>>>(Wcomb, gW1, gW2,
                                                           (__nv_bfloat16*)wt);

    // --- initial embedding + combine MLP (K=256 split into two K=128 GEMMs) ---
    build_embed_kernel<<<(NN * 64 + 255) / 256, 256>>>(z, pos, tab, Wp, bp, E0, E1);
    gemm_tc_kernel<false, false, false><<<gemm_grid, 256, GEMM_SMEM>>>(
        E0, wt + 0 * mat_u4, nullptr, nullptr, y, NN);
    gemm_tc_kernel<true, true, true><<<gemm_grid, 256, GEMM_SMEM>>>(
        E1, wt + 1 * mat_u4, bcomb, y, x, NN);

    // --- GIN layers ---
    for (int l = 0; l < NL; l++) {
        gather_kernel<<<(NN + 7) / 8, 256>>>(x, rowptr, col, agg);
        gemm_tc_kernel<true, true, false><<<gemm_grid, 256, GEMM_SMEM>>>(
            agg, wt + (size_t)(2 + l) * mat_u4, gb1 + (size_t)l * H, nullptr, y, NN);
        if (l < NL - 1) {
            gemm_tc_kernel<true, true, false><<<gemm_grid, 256, GEMM_SMEM>>>(
                y, wt + (size_t)(6 + l) * mat_u4, gb2 + (size_t)l * H, nullptr, x, NN);
        } else {
            gemm_tc_kernel<false, true, false><<<gemm_grid, 256, GEMM_SMEM>>>(
                y, wt + (size_t)(6 + l) * mat_u4, gb2 + (size_t)l * H, nullptr, x, NN);
        }
    }

    // --- pooling / heads / epilogue ---
    pool_kernel<<<NG, 128>>>(x, batch, pool);
    heads_kernel<<<dim3(4, 32), 128>>>(pool, hW1, hb1, hW2, hb2, ho);
    final_kernel<<<2, 256>>>(ho, out);
}

// round 8
// speedup vs baseline: 2.0680x; 1.4307x over previous
#include <cuda_runtime.h>
#include <cuda_bf16.h>
#include <cstdint>

#define NN 50000
#define NE 800000
#define NG 512
#define H  128
#define NL 4

#define SCAN_B  128
#define SCAN_NB ((NN + SCAN_B - 1) / SCAN_B)   // 391

// padded bf16 row length for B tiles (ldmatrix-friendly, conflict-free)
#define LDK 136
#define PLANE (128 * LDK)                      // elements per plane
#define BBYTES (PLANE * 2 * 2)                 // hi+lo planes, bytes (69632)

// ---------------- device scratch (static, no allocations) ----------------
__device__ float g_E  [(size_t)NN * 2 * H];
__device__ float g_x  [(size_t)NN * H];
__device__ float g_y  [(size_t)NN * H];
__device__ float g_agg[(size_t)NN * H];
__device__ float g_pool[(size_t)NG * H];
__device__ float g_ho [4 * NG];
// pre-split weights: 10 matrices x (hi plane + lo plane), [n][LDK] bf16
__device__ uint4 g_wt[(size_t)10 * BBYTES / 16];
// CSR scratch
__device__ int g_deg   [NN];
__device__ int g_rowptr[NN + 1];
__device__ int g_cursor[NN];
__device__ int g_col   [NE];
__device__ int g_part  [SCAN_NB];

// ---------------- helpers ----------------
__device__ __forceinline__ uint32_t smem_to_u32(const void* p) {
    uint32_t a;
    asm("{ .reg .u64 t; cvta.to.shared.u64 t, %1; cvt.u32.u64 %0, t; }" : "=r"(a) : "l"(p));
    return a;
}
__device__ __forceinline__ uint32_t pack_bf16x2(float lo_elem, float hi_elem) {
    uint32_t r;
    asm("cvt.rn.bf16x2.f32 %0, %1, %2;" : "=r"(r) : "f"(hi_elem), "f"(lo_elem));
    return r;
}
// split a float2 into hi/lo bf16x2 fragments
__device__ __forceinline__ void split2(float2 f, uint32_t& hi, uint32_t& lo) {
    hi = pack_bf16x2(f.x, f.y);
    float hx = __uint_as_float(hi << 16);
    float hy = __uint_as_float(hi & 0xFFFF0000u);
    lo = pack_bf16x2(f.x - hx, f.y - hy);
}
__device__ __forceinline__ void ldsm_x2(uint32_t addr, uint32_t& r0, uint32_t& r1) {
    asm volatile("ldmatrix.sync.aligned.m8n8.x2.shared.b16 {%0,%1}, [%2];"
                 : "=r"(r0), "=r"(r1) : "r"(addr));
}
__device__ __forceinline__ void mma16816(float* c, const uint32_t* a, const uint32_t* b) {
    asm volatile("mma.sync.aligned.m16n8k16.row.col.f32.bf16.bf16.f32 "
                 "{%0,%1,%2,%3}, {%4,%5,%6,%7}, {%8,%9}, {%0,%1,%2,%3};"
                 : "+f"(c[0]), "+f"(c[1]), "+f"(c[2]), "+f"(c[3])
                 : "r"(a[0]), "r"(a[1]), "r"(a[2]), "r"(a[3]), "r"(b[0]), "r"(b[1]));
}
__device__ __forceinline__ float softplusf(float x) {
    return fmaxf(x, 0.f) + log1pf(expf(-fabsf(x)));
}
__device__ __forceinline__ int lbound(const int* __restrict__ a, int n, int v) {
    int lo = 0, hi = n;
    while (lo < hi) { int m = (lo + hi) >> 1; if (a[m] < v) lo = m + 1; else hi = m; }
    return lo;
}

// ---------------- CSR build ----------------
__global__ void zero_int_kernel(int* __restrict__ p, int n) {
    int i = blockIdx.x * blockDim.x + threadIdx.x;
    if (i < n) p[i] = 0;
}
__global__ void deg_kernel(const int* __restrict__ dst, int* __restrict__ deg) {
    int e = blockIdx.x * blockDim.x + threadIdx.x;
    if (e < NE) atomicAdd(deg + dst[e], 1);
}
__global__ void partial_kernel(const int* __restrict__ deg, int* __restrict__ part) {
    __shared__ int sh[SCAN_B];
    int b = blockIdx.x, t = threadIdx.x, i = b * SCAN_B + t;
    sh[t] = (i < NN) ? deg[i] : 0;
    __syncthreads();
    for (int off = SCAN_B / 2; off > 0; off >>= 1) {
        if (t < off) sh[t] += sh[t + off];
        __syncthreads();
    }
    if (t == 0) part[b] = sh[0];
}
__global__ void scanpart_kernel(int* __restrict__ part, int* __restrict__ rowptr) {
    __shared__ int sh[512];
    int t = threadIdx.x;
    sh[t] = (t < SCAN_NB) ? part[t] : 0;
    __syncthreads();
    for (int off = 1; off < 512; off <<= 1) {
        int v = (t >= off) ? sh[t - off] : 0;
        __syncthreads();
        sh[t] += v;
        __syncthreads();
    }
    if (t < SCAN_NB) part[t] = (t == 0) ? 0 : sh[t - 1];
    if (t == 0) rowptr[NN] = NE;
}
__global__ void rowptr_kernel(const int* __restrict__ deg, const int* __restrict__ part,
                              int* __restrict__ rowptr, int* __restrict__ cursor) {
    __shared__ int sh[SCAN_B];
    int b = blockIdx.x, t = threadIdx.x, i = b * SCAN_B + t;
    sh[t] = (i < NN) ? deg[i] : 0;
    __syncthreads();
    for (int off = 1; off < SCAN_B; off <<= 1) {
        int v = (t >= off) ? sh[t - off] : 0;
        __syncthreads();
        sh[t] += v;
        __syncthreads();
    }
    if (i < NN) {
        int excl = part[b] + ((t == 0) ? 0 : sh[t - 1]);
        rowptr[i] = excl;
        cursor[i] = excl;
    }
}
__global__ void fill_kernel(const int* __restrict__ src, const int* __restrict__ dst,
                            int* __restrict__ cursor, int* __restrict__ col) {
    int e = blockIdx.x * blockDim.x + threadIdx.x;
    if (e < NE) {
        int p = atomicAdd(cursor + dst[e], 1);
        col[p] = src[e];
    }
}

// ---------------- gather: agg[i] = x[i] + sum_{j in N(i)} x[j] (unroll 4, MLP) ----------------
__global__ __launch_bounds__(256)
void gather_kernel(const float* __restrict__ x, const int* __restrict__ rowptr,
                   const int* __restrict__ col, float* __restrict__ agg) {
    int node = blockIdx.x * 8 + (threadIdx.x >> 5);
    if (node >= NN) return;
    int lane = threadIdx.x & 31;
    int beg = rowptr[node];
    int end = rowptr[node + 1];
    const float* xr = x + (size_t)lane * 4;
    float4 acc = *(const float4*)(x + (size_t)node * H + lane * 4);
    float4 acc2 = make_float4(0.f, 0.f, 0.f, 0.f);
    int j = beg;
    for (; j + 3 < end; j += 4) {
        int s0 = col[j], s1 = col[j + 1], s2 = col[j + 2], s3 = col[j + 3];
        float4 a = *(const float4*)(xr + (size_t)s0 * H);
        float4 b = *(const float4*)(xr + (size_t)s1 * H);
        float4 c = *(const float4*)(xr + (size_t)s2 * H);
        float4 d = *(const float4*)(xr + (size_t)s3 * H);
        acc.x += a.x + b.x;  acc.y += a.y + b.y;
        acc.z += a.z + b.z;  acc.w += a.w + b.w;
        acc2.x += c.x + d.x; acc2.y += c.y + d.y;
        acc2.z += c.z + d.z; acc2.w += c.w + d.w;
    }
    for (; j < end; j++) {
        int s0 = col[j];
        float4 a = *(const float4*)(xr + (size_t)s0 * H);
        acc.x += a.x; acc.y += a.y; acc.z += a.z; acc.w += a.w;
    }
    acc.x += acc2.x; acc.y += acc2.y; acc.z += acc2.z; acc.w += acc2.w;
    *(float4*)(agg + (size_t)node * H + lane * 4) = acc;
}

// ---------------- embed ----------------
__global__ void build_embed_kernel(const int* __restrict__ z, const float* __restrict__ pos,
                                   const float* __restrict__ tab, const float* __restrict__ Wp,
                                   const float* __restrict__ bp,
                                   float* __restrict__ E0, float* __restrict__ E1) {
    int gid = blockIdx.x * blockDim.x + threadIdx.x;
    if (gid >= NN * 64) return;
    int i = gid >> 6;
    int j = gid & 63;
    if (j < 32) {
        int c = j * 4;
        *(float4*)(E0 + (size_t)i * H + c) = *(const float4*)(tab + (size_t)z[i] * H + c);
    } else {
        int c = (j - 32) * 4;
        float p0 = pos[i * 3 + 0], p1 = pos[i * 3 + 1], p2 = pos[i * 3 + 2];
        float4 v;
        v.x = p0 * Wp[0 * H + c + 0] + p1 * Wp[1 * H + c + 0] + p2 * Wp[2 * H + c + 0] + bp[c + 0];
        v.y = p0 * Wp[0 * H + c + 1] + p1 * Wp[1 * H + c + 1] + p2 * Wp[2 * H + c + 1] + bp[c + 1];
        v.z = p0 * Wp[0 * H + c + 2] + p1 * Wp[1 * H + c + 2] + p2 * Wp[2 * H + c + 2] + bp[c + 2];
        v.w = p0 * Wp[0 * H + c + 3] + p1 * Wp[1 * H + c + 3] + p2 * Wp[2 * H + c + 3] + bp[c + 3];
        *(float4*)(E1 + (size_t)i * H + c) = v;
    }
}

// ---------------- weight prep: transpose + bf16 hi/lo split, padded [n][LDK] ----------------
__global__ void prep_weights_kernel(const float* __restrict__ Wcomb, const float* __restrict__ gW1,
                                    const float* __restrict__ gW2, __nv_bfloat16* __restrict__ wt) {
    int gid = blockIdx.x * blockDim.x + threadIdx.x;
    if (gid >= 10 * 16384) return;
    int mat = gid >> 14;
    int k   = (gid >> 7) & 127;
    int n   = gid & 127;
    const float* Wsrc = (mat < 2) ? Wcomb + (size_t)mat * 16384
                      : (mat < 6) ? gW1 + (size_t)(mat - 2) * 16384
                                  : gW2 + (size_t)(mat - 6) * 16384;
    float v = Wsrc[(size_t)k * 128 + n];       // B[n][k] = W[k][n]
    float h = __bfloat162float(__float2bfloat16(v));
    float l = v - h;
    __nv_bfloat16* base = wt + (size_t)mat * 2 * PLANE;
    base[(size_t)n * LDK + k]         = __float2bfloat16(h);
    base[PLANE + (size_t)n * LDK + k] = __float2bfloat16(l);
}

// ---------------- HMMA GEMM: C[M,128] = act(A[M,128] @ W + bias (+ Cin)) ----------------
// A fragments built directly from gmem (L2-hot) with in-register hi/lo split.
// B (hi+lo planes) staged in smem via cp.async. 2 CTAs/SM for phase overlap.
#define SM_B_HI 0
#define SM_B_LO (PLANE * 2)
#define GEMM_SMEM BBYTES        // 69632 bytes

template<bool RELU, bool BIAS, bool ADDC>
__global__ __launch_bounds__(256, 2)
void gemm_tc_kernel(const float* __restrict__ A, const uint4* __restrict__ Bt,
                    const float* __restrict__ bias, const float* __restrict__ Cin,
                    float* __restrict__ C, int M) {
    extern __shared__ char smem[];
    uint32_t sb = smem_to_u32(smem);
    int t = threadIdx.x, wid = t >> 5, lane = t & 31;
    int m0 = blockIdx.x * 128;

    // async copy of pre-split B (hi+lo)
    for (int i = t; i < BBYTES / 16; i += 256) {
        uint32_t d = sb + i * 16;
        asm volatile("cp.async.cg.shared.global [%0], [%1], 16;"
                     :: "r"(d), "l"(Bt + i) : "memory");
    }
    asm volatile("cp.async.commit_group;\ncp.async.wait_group 0;" ::: "memory");
    __syncthreads();

    // warp tile: 32 rows x 64 cols
    int mrow0 = (wid >> 1) * 32;
    int ncol0 = (wid & 1) * 64;
    int g  = lane >> 2;       // 0..7
    int tg = (lane & 3) * 2;  // fragment k-col base

    // clamped A row pointers (rows beyond M compute garbage, stores guarded)
    int r0 = min(m0 + mrow0 + g,      M - 1);
    int r1 = min(m0 + mrow0 + g + 8,  M - 1);
    int r2 = min(m0 + mrow0 + g + 16, M - 1);
    int r3 = min(m0 + mrow0 + g + 24, M - 1);
    const float* p00 = A + (size_t)r0 * 128 + tg;
    const float* p01 = A + (size_t)r1 * 128 + tg;
    const float* p10 = A + (size_t)r2 * 128 + tg;
    const float* p11 = A + (size_t)r3 * 128 + tg;

    // B ldmatrix base address (lanes 0..15 used by x2)
    uint32_t boff = ((uint32_t)(ncol0 + ((lane & 15) & 7)) * LDK + ((lane >> 3) & 1) * 8) * 2;
    uint32_t aBh = sb + SM_B_HI + boff;
    uint32_t aBl = sb + SM_B_LO + boff;

    float acc[2][8][4];
#pragma unroll
    for (int mi = 0; mi < 2; mi++)
#pragma unroll
        for (int nf = 0; nf < 8; nf++)
#pragma unroll
            for (int q = 0; q < 4; q++) acc[mi][nf][q] = 0.f;

#pragma unroll
    for (int kk = 0; kk < 8; kk++) {
        int k = kk * 16;
        uint32_t ko = kk * 32;           // bytes
        uint32_t ah[2][4], al[2][4];
        // build A fragments from gmem: a0=(g,k..), a1=(g+8), a2=(g,k+8), a3=(g+8,k+8)
        {
            float2 f0 = *(const float2*)(p00 + k);
            float2 f1 = *(const float2*)(p01 + k);
            float2 f2 = *(const float2*)(p00 + k + 8);
            float2 f3 = *(const float2*)(p01 + k + 8);
            split2(f0, ah[0][0], al[0][0]);
            split2(f1, ah[0][1], al[0][1]);
            split2(f2, ah[0][2], al[0][2]);
            split2(f3, ah[0][3], al[0][3]);
            f0 = *(const float2*)(p10 + k);
            f1 = *(const float2*)(p11 + k);
            f2 = *(const float2*)(p10 + k + 8);
            f3 = *(const float2*)(p11 + k + 8);
            split2(f0, ah[1][0], al[1][0]);
            split2(f1, ah[1][1], al[1][1]);
            split2(f2, ah[1][2], al[1][2]);
            split2(f3, ah[1][3], al[1][3]);
        }
#pragma unroll
        for (int nf = 0; nf < 8; nf++) {
            uint32_t bh[2], bl[2];
            ldsm_x2(aBh + nf * (8 * LDK * 2) + ko, bh[0], bh[1]);
            ldsm_x2(aBl + nf * (8 * LDK * 2) + ko, bl[0], bl[1]);
#pragma unroll
            for (int mi = 0; mi < 2; mi++) {
                mma16816(acc[mi][nf], ah[mi], bh);
                mma16816(acc[mi][nf], ah[mi], bl);
                mma16816(acc[mi][nf], al[mi], bh);
            }
        }
    }

    // epilogue
    int rbase = mrow0 + (lane >> 2);
    int cbase = ncol0 + (lane & 3) * 2;
#pragma unroll
    for (int mi = 0; mi < 2; mi++) {
#pragma unroll
        for (int half = 0; half < 2; half++) {
            int row = rbase + mi * 16 + half * 8;
            int m = m0 + row;
            if (m >= M) continue;
#pragma unroll
            for (int nf = 0; nf < 8; nf++) {
                int colc = cbase + nf * 8;
                float2 v;
                v.x = acc[mi][nf][half * 2 + 0];
                v.y = acc[mi][nf][half * 2 + 1];
                if (BIAS) {
                    float2 b2 = *(const float2*)(bias + colc);
                    v.x += b2.x; v.y += b2.y;
                }
                if (ADDC) {
                    float2 c2 = *(const float2*)(Cin + (size_t)m * 128 + colc);
                    v.x += c2.x; v.y += c2.y;
                }
                if (RELU) { v.x = fmaxf(v.x, 0.f); v.y = fmaxf(v.y, 0.f); }
                *(float2*)(C + (size_t)m * 128 + colc) = v;
            }
        }
    }
}

// ---------------- pooling / heads / epilogue ----------------
__global__ void pool_kernel(const float* __restrict__ x, const int* __restrict__ batch,
                            float* __restrict__ pool) {
    int g = blockIdx.x, f = threadIdx.x;
    __shared__ int slo, shi;
    if (f == 0) { slo = lbound(batch, NN, g); shi = lbound(batch, NN, g + 1); }
    __syncthreads();
    float s = 0.f;
    for (int i = slo; i < shi; i++) s += x[(size_t)i * H + f];
    pool[(size_t)g * H + f] = s;
}

__global__ void heads_kernel(const float* __restrict__ pool, const float* __restrict__ W1,
                             const float* __restrict__ b1, const float* __restrict__ W2,
                             const float* __restrict__ b2, float* __restrict__ hout) {
    int k = blockIdx.x, gc = blockIdx.y, f = threadIdx.x;
    __shared__ float rows[16][128];
    __shared__ float red[16][128];
    int g0 = gc * 16;
#pragma unroll
    for (int g = 0; g < 16; g++) rows[g][f] = pool[(size_t)(g0 + g) * H + f];
    __syncthreads();
    const float* W1k = W1 + (size_t)k * H * H;
    float acc[16];
#pragma unroll
    for (int g = 0; g < 16; g++) acc[g] = 0.f;
    for (int h = 0; h < 128; h++) {
        float w = W1k[(size_t)h * H + f];
#pragma unroll
        for (int g = 0; g < 16; g++) acc[g] = fmaf(rows[g][h], w, acc[g]);
    }
    float bb = b1[k * H + f];
    float w2 = W2[k * H + f];
#pragma unroll
    for (int g = 0; g < 16; g++) red[g][f] = fmaxf(acc[g] + bb, 0.f) * w2;
    __syncthreads();
    if (f < 16) {
        float s = 0.f;
        for (int h = 0; h < 128; h++) s += red[f][h];
        hout[k * NG + g0 + f] = s + b2[k];
    }
}

__global__ void final_kernel(const float* __restrict__ ho, float* __restrict__ out) {
    int g = blockIdx.x * blockDim.x + threadIdx.x;
    if (g >= NG) return;
    float o0 = ho[0 * NG + g], o1 = ho[1 * NG + g];
    float o2 = ho[2 * NG + g], o3 = ho[3 * NG + g];
    float alpha = fmaxf(softplusf(o0) + 1.f, 1.f + 1e-4f);
    float beta  = softplusf(o1);
    float nu    = softplusf(o2);
    float am1   = alpha - 1.f;
    out[0 * NG + g] = o3;
    out[1 * NG + g] = beta / am1;
    out[2 * NG + g] = beta / (am1 * nu);
    out[3 * NG + g] = nu;
    out[4 * NG + g] = alpha;
    out[5 * NG + g] = beta;
}

// ---------------- launch ----------------
extern "C" void kernel_launch(void* const* d_in, const int* in_sizes, int n_in,
                              void* d_out, int out_size) {
    const int*   z      = (const int*)  d_in[0];
    const float* pos    = (const float*)d_in[1];
    const int*   batch  = (const int*)  d_in[2];
    const int*   eidx   = (const int*)  d_in[3];
    const float* tab    = (const float*)d_in[4];
    const float* Wp     = (const float*)d_in[5];
    const float* bp     = (const float*)d_in[6];
    const float* Wcomb  = (const float*)d_in[7];
    const float* bcomb  = (const float*)d_in[8];
    const float* gW1    = (const float*)d_in[9];
    const float* gb1    = (const float*)d_in[10];
    const float* gW2    = (const float*)d_in[11];
    const float* gb2    = (const float*)d_in[12];
    const float* hW1    = (const float*)d_in[13];
    const float* hb1    = (const float*)d_in[14];
    const float* hW2    = (const float*)d_in[15];
    const float* hb2    = (const float*)d_in[16];
    float* out = (float*)d_out;

    float *E, *x, *y, *agg, *pool, *ho;
    uint4* wt;
    int *deg, *rowptr, *cursor, *col, *part;
    cudaGetSymbolAddress((void**)&E,      g_E);
    cudaGetSymbolAddress((void**)&x,      g_x);
    cudaGetSymbolAddress((void**)&y,      g_y);
    cudaGetSymbolAddress((void**)&agg,    g_agg);
    cudaGetSymbolAddress((void**)&pool,   g_pool);
    cudaGetSymbolAddress((void**)&ho,     g_ho);
    cudaGetSymbolAddress((void**)&wt,     g_wt);
    cudaGetSymbolAddress((void**)&deg,    g_deg);
    cudaGetSymbolAddress((void**)&rowptr, g_rowptr);
    cudaGetSymbolAddress((void**)&cursor, g_cursor);
    cudaGetSymbolAddress((void**)&col,    g_col);
    cudaGetSymbolAddress((void**)&part,   g_part);

    float* E0 = E;
    float* E1 = E + (size_t)NN * H;

    cudaFuncSetAttribute(gemm_tc_kernel<false, false, false>, cudaFuncAttributeMaxDynamicSharedMemorySize, GEMM_SMEM);
    cudaFuncSetAttribute(gemm_tc_kernel<true,  true,  true >, cudaFuncAttributeMaxDynamicSharedMemorySize, GEMM_SMEM);
    cudaFuncSetAttribute(gemm_tc_kernel<true,  true,  false>, cudaFuncAttributeMaxDynamicSharedMemorySize, GEMM_SMEM);
    cudaFuncSetAttribute(gemm_tc_kernel<false, true,  false>, cudaFuncAttributeMaxDynamicSharedMemorySize, GEMM_SMEM);

    const int gemm_grid = (NN + 127) / 128;   // 391
    const int* src = eidx;
    const int* dst = eidx + NE;
    const size_t mat_u4 = BBYTES / 16;        // uint4 stride per matrix

    // --- front-loaded so launch #4 (the ncu-captured one) is a GEMM ---
    prep_weights_kernel<<<(10 * 16384 + 255) / 256, 256>>>(Wcomb, gW1, gW2,
                                                           (__nv_bfloat16*)wt);
    build_embed_kernel<<<(NN * 64 + 255) / 256, 256>>>(z, pos, tab, Wp, bp, E0, E1);
    gemm_tc_kernel<false, false, false><<<gemm_grid, 256, GEMM_SMEM>>>(
        E0, wt + 0 * mat_u4, nullptr, nullptr, y, NN);
    gemm_tc_kernel<true, true, true><<<gemm_grid, 256, GEMM_SMEM>>>(
        E1, wt + 1 * mat_u4, bcomb, y, x, NN);

    // --- CSR build (needed before first gather) ---
    zero_int_kernel<<<(NN + 255) / 256, 256>>>(deg, NN);
    deg_kernel<<<(NE + 255) / 256, 256>>>(dst, deg);
    partial_kernel<<<SCAN_NB, SCAN_B>>>(deg, part);
    scanpart_kernel<<<1, 512>>>(part, rowptr);
    rowptr_kernel<<<SCAN_NB, SCAN_B>>>(deg, part, rowptr, cursor);
    fill_kernel<<<(NE + 255) / 256, 256>>>(src, dst, cursor, col);

    // --- GIN layers ---
    for (int l = 0; l < NL; l++) {
        gather_kernel<<<(NN + 7) / 8, 256>>>(x, rowptr, col, agg);
        gemm_tc_kernel<true, true, false><<<gemm_grid, 256, GEMM_SMEM>>>(
            agg, wt + (size_t)(2 + l) * mat_u4, gb1 + (size_t)l * H, nullptr, y, NN);
        if (l < NL - 1) {
            gemm_tc_kernel<true, true, false><<<gemm_grid, 256, GEMM_SMEM>>>(
                y, wt + (size_t)(6 + l) * mat_u4, gb2 + (size_t)l * H, nullptr, x, NN);
        } else {
            gemm_tc_kernel<false, true, false><<<gemm_grid, 256, GEMM_SMEM>>>(
                y, wt + (size_t)(6 + l) * mat_u4, gb2 + (size_t)l * H, nullptr, x, NN);
        }
    }

    // --- pooling / heads / epilogue ---
    pool_kernel<<<NG, 128>>>(x, batch, pool);
    heads_kernel<<<dim3(4, 32), 128>>>(pool, hW1, hb1, hW2, hb2, ho);
    final_kernel<<<2, 256>>>(ho, out);
}

// round 10
// speedup vs baseline: 2.3410x; 1.1320x over previous
#include <cuda_runtime.h>
#include <cuda_bf16.h>
#include <cstdint>

#define NN 50000
#define NE 800000
#define NG 512
#define H  128
#define NL 4

#define SCAN_B  128
#define SCAN_NB ((NN + SCAN_B - 1) / SCAN_B)   // 391

// padded bf16 row length for B tiles (ldmatrix-friendly, conflict-free)
#define LDK 136
#define PLANE (128 * LDK)                      // elements per plane
#define BBYTES (PLANE * 2 * 2)                 // hi+lo planes, bytes (69632)

// ---------------- device scratch (static, no allocations) ----------------
__device__ float g_x  [(size_t)NN * H];
__device__ float g_y  [(size_t)NN * H];
__device__ float g_agg[(size_t)NN * H];
__device__ float g_pool[(size_t)NG * H];
__device__ float g_ho [4 * NG];
__device__ float g_T   [100 * H];     // embed_tab @ Wc0
__device__ float g_Weff[3 * H];       // W_pos @ Wc1
__device__ float g_beff[H];           // b_pos @ Wc1 + b_comb
// pre-split weights: 8 matrices x (hi plane + lo plane), [n][LDK] bf16
__device__ uint4 g_wt[(size_t)8 * BBYTES / 16];
// CSR scratch
__device__ int g_deg   [NN];
__device__ int g_rowptr[NN + 1];
__device__ int g_cursor[NN];
__device__ int g_col   [NE];
__device__ int g_part  [SCAN_NB];

// ---------------- helpers ----------------
__device__ __forceinline__ uint32_t smem_to_u32(const void* p) {
    uint32_t a;
    asm("{ .reg .u64 t; cvta.to.shared.u64 t, %1; cvt.u32.u64 %0, t; }" : "=r"(a) : "l"(p));
    return a;
}
__device__ __forceinline__ uint32_t pack_bf16x2(float lo_elem, float hi_elem) {
    uint32_t r;
    asm("cvt.rn.bf16x2.f32 %0, %1, %2;" : "=r"(r) : "f"(hi_elem), "f"(lo_elem));
    return r;
}
__device__ __forceinline__ void split2(float2 f, uint32_t& hi, uint32_t& lo) {
    hi = pack_bf16x2(f.x, f.y);
    float hx = __uint_as_float(hi << 16);
    float hy = __uint_as_float(hi & 0xFFFF0000u);
    lo = pack_bf16x2(f.x - hx, f.y - hy);
}
__device__ __forceinline__ void ldsm_x2(uint32_t addr, uint32_t& r0, uint32_t& r1) {
    asm volatile("ldmatrix.sync.aligned.m8n8.x2.shared.b16 {%0,%1}, [%2];"
                 : "=r"(r0), "=r"(r1) : "r"(addr));
}
__device__ __forceinline__ void mma16816(float* c, const uint32_t* a, const uint32_t* b) {
    asm volatile("mma.sync.aligned.m16n8k16.row.col.f32.bf16.bf16.f32 "
                 "{%0,%1,%2,%3}, {%4,%5,%6,%7}, {%8,%9}, {%0,%1,%2,%3};"
                 : "+f"(c[0]), "+f"(c[1]), "+f"(c[2]), "+f"(c[3])
                 : "r"(a[0]), "r"(a[1]), "r"(a[2]), "r"(a[3]), "r"(b[0]), "r"(b[1]));
}
__device__ __forceinline__ float softplusf(float x) {
    return fmaxf(x, 0.f) + log1pf(expf(-fabsf(x)));
}
__device__ __forceinline__ int lbound(const int* __restrict__ a, int n, int v) {
    int lo = 0, hi = n;
    while (lo < hi) { int m = (lo + hi) >> 1; if (a[m] < v) lo = m + 1; else hi = m; }
    return lo;
}

// ---------------- init-stage folding ----------------
// T = tab @ Wc0 (100x128); Weff = W_pos @ Wc1 (3x128); beff = b_pos@Wc1 + b_comb
__global__ void prep_init_kernel(const float* __restrict__ tab, const float* __restrict__ Wp,
                                 const float* __restrict__ bp, const float* __restrict__ Wcomb,
                                 const float* __restrict__ bcomb,
                                 float* __restrict__ T, float* __restrict__ Weff,
                                 float* __restrict__ beff) {
    int gid = blockIdx.x * blockDim.x + threadIdx.x;
    if (gid >= 104 * H) return;
    int r = gid >> 7;
    int c = gid & 127;
    if (r < 100) {
        float s = 0.f;
        for (int k = 0; k < H; k++) s = fmaf(tab[(size_t)r * H + k], Wcomb[(size_t)k * H + c], s);
        T[(size_t)r * H + c] = s;
    } else if (r < 103) {
        int d = r - 100;
        float s = 0.f;
        for (int k = 0; k < H; k++) s = fmaf(Wp[(size_t)d * H + k], Wcomb[(size_t)(H + k) * H + c], s);
        Weff[(size_t)d * H + c] = s;
    } else {
        float s = bcomb[c];
        for (int k = 0; k < H; k++) s = fmaf(bp[k], Wcomb[(size_t)(H + k) * H + c], s);
        beff[c] = s;
    }
}

// x[i] = relu(T[z[i]] + pos[i] @ Weff + beff)
__global__ void x_init_kernel(const int* __restrict__ z, const float* __restrict__ pos,
                              const float* __restrict__ T, const float* __restrict__ Weff,
                              const float* __restrict__ beff, float* __restrict__ x) {
    int gid = blockIdx.x * blockDim.x + threadIdx.x;
    if (gid >= NN * 32) return;
    int i = gid >> 5;
    int c = (gid & 31) * 4;
    float p0 = pos[i * 3 + 0], p1 = pos[i * 3 + 1], p2 = pos[i * 3 + 2];
    float4 tv = *(const float4*)(T + (size_t)z[i] * H + c);
    float4 w0 = *(const float4*)(Weff + 0 * H + c);
    float4 w1 = *(const float4*)(Weff + 1 * H + c);
    float4 w2 = *(const float4*)(Weff + 2 * H + c);
    float4 bb = *(const float4*)(beff + c);
    float4 v;
    v.x = fmaxf(tv.x + p0 * w0.x + p1 * w1.x + p2 * w2.x + bb.x, 0.f);
    v.y = fmaxf(tv.y + p0 * w0.y + p1 * w1.y + p2 * w2.y + bb.y, 0.f);
    v.z = fmaxf(tv.z + p0 * w0.z + p1 * w1.z + p2 * w2.z + bb.z, 0.f);
    v.w = fmaxf(tv.w + p0 * w0.w + p1 * w1.w + p2 * w2.w + bb.w, 0.f);
    *(float4*)(x + (size_t)i * H + c) = v;
}

// ---------------- CSR build ----------------
__global__ void zero_int_kernel(int* __restrict__ p, int n) {
    int i = blockIdx.x * blockDim.x + threadIdx.x;
    if (i < n) p[i] = 0;
}
__global__ void deg_kernel(const int* __restrict__ dst, int* __restrict__ deg) {
    int e = blockIdx.x * blockDim.x + threadIdx.x;
    if (e < NE) atomicAdd(deg + dst[e], 1);
}
__global__ void partial_kernel(const int* __restrict__ deg, int* __restrict__ part) {
    __shared__ int sh[SCAN_B];
    int b = blockIdx.x, t = threadIdx.x, i = b * SCAN_B + t;
    sh[t] = (i < NN) ? deg[i] : 0;
    __syncthreads();
    for (int off = SCAN_B / 2; off > 0; off >>= 1) {
        if (t < off) sh[t] += sh[t + off];
        __syncthreads();
    }
    if (t == 0) part[b] = sh[0];
}
__global__ void scanpart_kernel(int* __restrict__ part, int* __restrict__ rowptr) {
    __shared__ int sh[512];
    int t = threadIdx.x;
    sh[t] = (t < SCAN_NB) ? part[t] : 0;
    __syncthreads();
    for (int off = 1; off < 512; off <<= 1) {
        int v = (t >= off) ? sh[t - off] : 0;
        __syncthreads();
        sh[t] += v;
        __syncthreads();
    }
    if (t < SCAN_NB) part[t] = (t == 0) ? 0 : sh[t - 1];
    if (t == 0) rowptr[NN] = NE;
}
__global__ void rowptr_kernel(const int* __restrict__ deg, const int* __restrict__ part,
                              int* __restrict__ rowptr, int* __restrict__ cursor) {
    __shared__ int sh[SCAN_B];
    int b = blockIdx.x, t = threadIdx.x, i = b * SCAN_B + t;
    sh[t] = (i < NN) ? deg[i] : 0;
    __syncthreads();
    for (int off = 1; off < SCAN_B; off <<= 1) {
        int v = (t >= off) ? sh[t - off] : 0;
        __syncthreads();
        sh[t] += v;
        __syncthreads();
    }
    if (i < NN) {
        int excl = part[b] + ((t == 0) ? 0 : sh[t - 1]);
        rowptr[i] = excl;
        cursor[i] = excl;
    }
}
__global__ void fill_kernel(const int* __restrict__ src, const int* __restrict__ dst,
                            int* __restrict__ cursor, int* __restrict__ col) {
    int e = blockIdx.x * blockDim.x + threadIdx.x;
    if (e < NE) {
        int p = atomicAdd(cursor + dst[e], 1);
        col[p] = src[e];
    }
}

// ---------------- gather: agg[i] = x[i] + sum_{j in N(i)} x[j] ----------------
__global__ __launch_bounds__(256)
void gather_kernel(const float* __restrict__ x, const int* __restrict__ rowptr,
                   const int* __restrict__ col, float* __restrict__ agg) {
    int node = blockIdx.x * 8 + (threadIdx.x >> 5);
    if (node >= NN) return;
    int lane = threadIdx.x & 31;
    int beg = rowptr[node];
    int end = rowptr[node + 1];
    const float* xr = x + (size_t)lane * 4;
    float4 acc = *(const float4*)(x + (size_t)node * H + lane * 4);
    float4 acc2 = make_float4(0.f, 0.f, 0.f, 0.f);
    int j = beg;
    for (; j + 3 < end; j += 4) {
        int s0 = col[j], s1 = col[j + 1], s2 = col[j + 2], s3 = col[j + 3];
        float4 a = *(const float4*)(xr + (size_t)s0 * H);
        float4 b = *(const float4*)(xr + (size_t)s1 * H);
        float4 c = *(const float4*)(xr + (size_t)s2 * H);
        float4 d = *(const float4*)(xr + (size_t)s3 * H);
        acc.x += a.x + b.x;  acc.y += a.y + b.y;
        acc.z += a.z + b.z;  acc.w += a.w + b.w;
        acc2.x += c.x + d.x; acc2.y += c.y + d.y;
        acc2.z += c.z + d.z; acc2.w += c.w + d.w;
    }
    for (; j < end; j++) {
        int s0 = col[j];
        float4 a = *(const float4*)(xr + (size_t)s0 * H);
        acc.x += a.x; acc.y += a.y; acc.z += a.z; acc.w += a.w;
    }
    acc.x += acc2.x; acc.y += acc2.y; acc.z += acc2.z; acc.w += acc2.w;
    *(float4*)(agg + (size_t)node * H + lane * 4) = acc;
}

// ---------------- weight prep: transpose + bf16 hi/lo split, padded [n][LDK] ----------------
// mat 0..3: gin_W1[l]; 4..7: gin_W2[l]
__global__ void prep_weights_kernel(const float* __restrict__ gW1, const float* __restrict__ gW2,
                                    __nv_bfloat16* __restrict__ wt) {
    int gid = blockIdx.x * blockDim.x + threadIdx.x;
    if (gid >= 8 * 16384) return;
    int mat = gid >> 14;
    int k   = (gid >> 7) & 127;
    int n   = gid & 127;
    const float* Wsrc = (mat < 4) ? gW1 + (size_t)mat * 16384
                                  : gW2 + (size_t)(mat - 4) * 16384;
    float v = Wsrc[(size_t)k * 128 + n];       // B[n][k] = W[k][n]
    float h = __bfloat162float(__float2bfloat16(v));
    float l = v - h;
    __nv_bfloat16* base = wt + (size_t)mat * 2 * PLANE;
    base[(size_t)n * LDK + k]         = __float2bfloat16(h);
    base[PLANE + (size_t)n * LDK + k] = __float2bfloat16(l);
}

// ---------------- HMMA GEMM: C[M,128] = act(A[M,128] @ W + bias) ----------------
// A fragments from gmem with explicit double-buffered prefetch + in-register
// hi/lo split. B (hi+lo planes) in smem via cp.async. 2 CTAs/SM.
#define SM_B_HI 0
#define SM_B_LO (PLANE * 2)
#define GEMM_SMEM BBYTES        // 69632 bytes

template<bool RELU>
__global__ __launch_bounds__(256, 2)
void gemm_tc_kernel(const float* __restrict__ A, const uint4* __restrict__ Bt,
                    const float* __restrict__ bias, float* __restrict__ C, int M) {
    extern __shared__ char smem[];
    uint32_t sb = smem_to_u32(smem);
    int t = threadIdx.x, wid = t >> 5, lane = t & 31;
    int m0 = blockIdx.x * 128;

    // async copy of pre-split B (hi+lo)
    for (int i = t; i < BBYTES / 16; i += 256) {
        uint32_t d = sb + i * 16;
        asm volatile("cp.async.cg.shared.global [%0], [%1], 16;"
                     :: "r"(d), "l"(Bt + i) : "memory");
    }
    asm volatile("cp.async.commit_group;" ::: "memory");

    // warp tile: 32 rows x 64 cols
    int mrow0 = (wid >> 1) * 32;
    int ncol0 = (wid & 1) * 64;
    int g  = lane >> 2;
    int tg = (lane & 3) * 2;

    int r0 = min(m0 + mrow0 + g,      M - 1);
    int r1 = min(m0 + mrow0 + g + 8,  M - 1);
    int r2 = min(m0 + mrow0 + g + 16, M - 1);
    int r3 = min(m0 + mrow0 + g + 24, M - 1);
    const float* p00 = A + (size_t)r0 * 128 + tg;
    const float* p01 = A + (size_t)r1 * 128 + tg;
    const float* p10 = A + (size_t)r2 * 128 + tg;
    const float* p11 = A + (size_t)r3 * 128 + tg;

    // issue A loads for kk=0 while B's cp.async is in flight
    float2 cur[8];
    cur[0] = *(const float2*)(p00);     cur[1] = *(const float2*)(p00 + 8);
    cur[2] = *(const float2*)(p01);     cur[3] = *(const float2*)(p01 + 8);
    cur[4] = *(const float2*)(p10);     cur[5] = *(const float2*)(p10 + 8);
    cur[6] = *(const float2*)(p11);     cur[7] = *(const float2*)(p11 + 8);

    asm volatile("cp.async.wait_group 0;" ::: "memory");
    __syncthreads();

    uint32_t boff = ((uint32_t)(ncol0 + ((lane & 15) & 7)) * LDK + ((lane >> 3) & 1) * 8) * 2;
    uint32_t aBh = sb + SM_B_HI + boff;
    uint32_t aBl = sb + SM_B_LO + boff;

    float acc[2][8][4];
#pragma unroll
    for (int mi = 0; mi < 2; mi++)
#pragma unroll
        for (int nf = 0; nf < 8; nf++)
#pragma unroll
            for (int q = 0; q < 4; q++) acc[mi][nf][q] = 0.f;

#pragma unroll
    for (int kk = 0; kk < 8; kk++) {
        uint32_t ko = kk * 32;           // bytes
        // prefetch raw A for kk+1
        float2 nxt[8];
        if (kk < 7) {
            int k2 = (kk + 1) * 16;
            nxt[0] = *(const float2*)(p00 + k2); nxt[1] = *(const float2*)(p00 + k2 + 8);
            nxt[2] = *(const float2*)(p01 + k2); nxt[3] = *(const float2*)(p01 + k2 + 8);
            nxt[4] = *(const float2*)(p10 + k2); nxt[5] = *(const float2*)(p10 + k2 + 8);
            nxt[6] = *(const float2*)(p11 + k2); nxt[7] = *(const float2*)(p11 + k2 + 8);
        }
        // split cur into fragments (a0=(g,k), a1=(g+8,k), a2=(g,k+8), a3=(g+8,k+8))
        uint32_t ah[2][4], al[2][4];
        split2(cur[0], ah[0][0], al[0][0]);
        split2(cur[2], ah[0][1], al[0][1]);
        split2(cur[1], ah[0][2], al[0][2]);
        split2(cur[3], ah[0][3], al[0][3]);
        split2(cur[4], ah[1][0], al[1][0]);
        split2(cur[6], ah[1][1], al[1][1]);
        split2(cur[5], ah[1][2], al[1][2]);
        split2(cur[7], ah[1][3], al[1][3]);
#pragma unroll
        for (int nf = 0; nf < 8; nf++) {
            uint32_t bh[2], bl[2];
            ldsm_x2(aBh + nf * (8 * LDK * 2) + ko, bh[0], bh[1]);
            ldsm_x2(aBl + nf * (8 * LDK * 2) + ko, bl[0], bl[1]);
#pragma unroll
            for (int mi = 0; mi < 2; mi++) {
                mma16816(acc[mi][nf], ah[mi], bh);
                mma16816(acc[mi][nf], ah[mi], bl);
                mma16816(acc[mi][nf], al[mi], bh);
            }
        }
#pragma unroll
        for (int j = 0; j < 8; j++) cur[j] = nxt[j];
    }

    // epilogue
    int rbase = mrow0 + (lane >> 2);
    int cbase = ncol0 + (lane & 3) * 2;
#pragma unroll
    for (int mi = 0; mi < 2; mi++) {
#pragma unroll
        for (int half = 0; half < 2; half++) {
            int row = rbase + mi * 16 + half * 8;
            int m = m0 + row;
            if (m >= M) continue;
#pragma unroll
            for (int nf = 0; nf < 8; nf++) {
                int colc = cbase + nf * 8;
                float2 v;
                v.x = acc[mi][nf][half * 2 + 0];
                v.y = acc[mi][nf][half * 2 + 1];
                float2 b2 = *(const float2*)(bias + colc);
                v.x += b2.x; v.y += b2.y;
                if (RELU) { v.x = fmaxf(v.x, 0.f); v.y = fmaxf(v.y, 0.f); }
                *(float2*)(C + (size_t)m * 128 + colc) = v;
            }
        }
    }
}

// ---------------- pooling / heads / epilogue ----------------
__global__ void pool_kernel(const float* __restrict__ x, const int* __restrict__ batch,
                            float* __restrict__ pool) {
    int g = blockIdx.x, f = threadIdx.x;
    __shared__ int slo, shi;
    if (f == 0) { slo = lbound(batch, NN, g); shi = lbound(batch, NN, g + 1); }
    __syncthreads();
    float s = 0.f;
    for (int i = slo; i < shi; i++) s += x[(size_t)i * H + f];
    pool[(size_t)g * H + f] = s;
}

__global__ void heads_kernel(const float* __restrict__ pool, const float* __restrict__ W1,
                             const float* __restrict__ b1, const float* __restrict__ W2,
                             const float* __restrict__ b2, float* __restrict__ hout) {
    int k = blockIdx.x, gc = blockIdx.y, f = threadIdx.x;
    __shared__ float rows[16][128];
    __shared__ float red[16][128];
    int g0 = gc * 16;
#pragma unroll
    for (int g = 0; g < 16; g++) rows[g][f] = pool[(size_t)(g0 + g) * H + f];
    __syncthreads();
    const float* W1k = W1 + (size_t)k * H * H;
    float acc[16];
#pragma unroll
    for (int g = 0; g < 16; g++) acc[g] = 0.f;
    for (int h = 0; h < 128; h++) {
        float w = W1k[(size_t)h * H + f];
#pragma unroll
        for (int g = 0; g < 16; g++) acc[g] = fmaf(rows[g][h], w, acc[g]);
    }
    float bb = b1[k * H + f];
    float w2 = W2[k * H + f];
#pragma unroll
    for (int g = 0; g < 16; g++) red[g][f] = fmaxf(acc[g] + bb, 0.f) * w2;
    __syncthreads();
    if (f < 16) {
        float s = 0.f;
        for (int h = 0; h < 128; h++) s += red[f][h];
        hout[k * NG + g0 + f] = s + b2[k];
    }
}

__global__ void final_kernel(const float* __restrict__ ho, float* __restrict__ out) {
    int g = blockIdx.x * blockDim.x + threadIdx.x;
    if (g >= NG) return;
    float o0 = ho[0 * NG + g], o1 = ho[1 * NG + g];
    float o2 = ho[2 * NG + g], o3 = ho[3 * NG + g];
    float alpha = fmaxf(softplusf(o0) + 1.f, 1.f + 1e-4f);
    float beta  = softplusf(o1);
    float nu    = softplusf(o2);
    float am1   = alpha - 1.f;
    out[0 * NG + g] = o3;
    out[1 * NG + g] = beta / am1;
    out[2 * NG + g] = beta / (am1 * nu);
    out[3 * NG + g] = nu;
    out[4 * NG + g] = alpha;
    out[5 * NG + g] = beta;
}

// ---------------- launch ----------------
extern "C" void kernel_launch(void* const* d_in, const int* in_sizes, int n_in,
                              void* d_out, int out_size) {
    const int*   z      = (const int*)  d_in[0];
    const float* pos    = (const float*)d_in[1];
    const int*   batch  = (const int*)  d_in[2];
    const int*   eidx   = (const int*)  d_in[3];
    const float* tab    = (const float*)d_in[4];
    const float* Wp     = (const float*)d_in[5];
    const float* bp     = (const float*)d_in[6];
    const float* Wcomb  = (const float*)d_in[7];
    const float* bcomb  = (const float*)d_in[8];
    const float* gW1    = (const float*)d_in[9];
    const float* gb1    = (const float*)d_in[10];
    const float* gW2    = (const float*)d_in[11];
    const float* gb2    = (const float*)d_in[12];
    const float* hW1    = (const float*)d_in[13];
    const float* hb1    = (const float*)d_in[14];
    const float* hW2    = (const float*)d_in[15];
    const float* hb2    = (const float*)d_in[16];
    float* out = (float*)d_out;

    float *x, *y, *agg, *pool, *ho, *T, *Weff, *beff;
    uint4* wt;
    int *deg, *rowptr, *cursor, *col, *part;
    cudaGetSymbolAddress((void**)&x,      g_x);
    cudaGetSymbolAddress((void**)&y,      g_y);
    cudaGetSymbolAddress((void**)&agg,    g_agg);
    cudaGetSymbolAddress((void**)&pool,   g_pool);
    cudaGetSymbolAddress((void**)&ho,     g_ho);
    cudaGetSymbolAddress((void**)&T,      g_T);
    cudaGetSymbolAddress((void**)&Weff,   g_Weff);
    cudaGetSymbolAddress((void**)&beff,   g_beff);
    cudaGetSymbolAddress((void**)&wt,     g_wt);
    cudaGetSymbolAddress((void**)&deg,    g_deg);
    cudaGetSymbolAddress((void**)&rowptr, g_rowptr);
    cudaGetSymbolAddress((void**)&cursor, g_cursor);
    cudaGetSymbolAddress((void**)&col,    g_col);
    cudaGetSymbolAddress((void**)&part,   g_part);

    cudaFuncSetAttribute(gemm_tc_kernel<true >, cudaFuncAttributeMaxDynamicSharedMemorySize, GEMM_SMEM);
    cudaFuncSetAttribute(gemm_tc_kernel<false>, cudaFuncAttributeMaxDynamicSharedMemorySize, GEMM_SMEM);

    const int gemm_grid = (NN + 127) / 128;   // 391
    const int* src = eidx;
    const int* dst = eidx + NE;
    const size_t mat_u4 = BBYTES / 16;        // uint4 stride per matrix

    // --- precompute (weights + folded init stage) ---
    prep_weights_kernel<<<(8 * 16384 + 255) / 256, 256>>>(gW1, gW2, (__nv_bfloat16*)wt);
    prep_init_kernel<<<(104 * H + 255) / 256, 256>>>(tab, Wp, bp, Wcomb, bcomb, T, Weff, beff);
    zero_int_kernel<<<(NN + 255) / 256, 256>>>(deg, NN);
    x_init_kernel<<<(NN * 32 + 255) / 256, 256>>>(z, pos, T, Weff, beff, x);

    // --- CSR build ---
    deg_kernel<<<(NE + 255) / 256, 256>>>(dst, deg);
    partial_kernel<<<SCAN_NB, SCAN_B>>>(deg, part);
    scanpart_kernel<<<1, 512>>>(part, rowptr);
    rowptr_kernel<<<SCAN_NB, SCAN_B>>>(deg, part, rowptr, cursor);
    fill_kernel<<<(NE + 255) / 256, 256>>>(src, dst, cursor, col);

    // --- GIN layers ---
    for (int l = 0; l < NL; l++) {
        gather_kernel<<<(NN + 7) / 8, 256>>>(x, rowptr, col, agg);
        gemm_tc_kernel<true><<<gemm_grid, 256, GEMM_SMEM>>>(
            agg, wt + (size_t)l * mat_u4, gb1 + (size_t)l * H, y, NN);
        if (l < NL - 1) {
            gemm_tc_kernel<true><<<gemm_grid, 256, GEMM_SMEM>>>(
                y, wt + (size_t)(4 + l) * mat_u4, gb2 + (size_t)l * H, x, NN);
        } else {
            gemm_tc_kernel<false><<<gemm_grid, 256, GEMM_SMEM>>>(
                y, wt + (size_t)(4 + l) * mat_u4, gb2 + (size_t)l * H, x, NN);
        }
    }

    // --- pooling / heads / epilogue ---
    pool_kernel<<<NG, 128>>>(x, batch, pool);
    heads_kernel<<<dim3(4, 32), 128>>>(pool, hW1, hb1, hW2, hb2, ho);
    final_kernel<<<2, 256>>>(ho, out);
}